// round 12
// baseline (speedup 1.0000x reference)
#include <cuda_runtime.h>
#include <cstdint>

typedef unsigned long long ull_t;

// packed fp32x2 FMA (sm_100+): two independent fp32 FMAs, bit-exact vs scalar
__device__ __forceinline__ float2 ffma2(float2 a, float2 b, float2 c) {
    float2 d;
    asm("fma.rn.f32x2 %0, %1, %2, %3;"
        : "=l"(reinterpret_cast<ull_t&>(d))
        : "l"(reinterpret_cast<ull_t&>(a)),
          "l"(reinterpret_cast<ull_t&>(b)),
          "l"(reinterpret_cast<ull_t&>(c)));
    return d;
}

// ---------------- scratch (device globals; no allocations allowed) ----------
__device__ float g_pool1[32 * 64 * 64 * 32];     // conv1+pool output
__device__ float g_conv2[32 * 64 * 64 * 64];     // conv2+relu output
__device__ float g_pmax[32 * 16 * 64];           // per (b,tile,c) partial max
__device__ int   g_pidx[32 * 16 * 64];           // per (b,tile,c) partial argmax
__device__ float g_psum[32 * 16 * 64];           // per (b,tile,c) partial sum
__device__ float g_part[128 * 32 * 1024];        // dense1 split-K partials
__device__ float g_hidden[32 * 1024];            // dense1 output (post relu)

// ---------------- K1: conv1 (3x3x1->32) + relu + 2x2 maxpool, 4ch/thread ----
__global__ void k_conv1_pool(const float* __restrict__ in,
                             const float* __restrict__ w,
                             const float* __restrict__ bias) {
    int idx = blockIdx.x * 256 + threadIdx.x;     // 32*64*64*8 = 1,048,576
    int cq = idx & 7;                             // channel quad: c = cq*4..+3
    int x = (idx >> 3) & 63;
    int y = (idx >> 9) & 63;
    int b = idx >> 15;

    float2 w0[9], w1[9];
#pragma unroll
    for (int i = 0; i < 9; i++) {
        float4 wv = *(const float4*)(w + i * 32 + cq * 4);
        w0[i].x = wv.x; w0[i].y = wv.y;
        w1[i].x = wv.z; w1[i].y = wv.w;
    }
    float4 bv = *(const float4*)(bias + cq * 4);
    float2 b0; b0.x = bv.x; b0.y = bv.y;
    float2 b1; b1.x = bv.z; b1.y = bv.w;
    const float* ib = in + b * 16384;

    float2 m0 = make_float2(0.f, 0.f), m1 = make_float2(0.f, 0.f);
#pragma unroll
    for (int sy = 0; sy < 2; sy++) {
#pragma unroll
        for (int sx = 0; sx < 2; sx++) {
            int oy = 2 * y + sy, ox = 2 * x + sx;
            float2 a0 = b0, a1 = b1;
#pragma unroll
            for (int ky = 0; ky < 3; ky++) {
                int yy = oy + ky - 1;
                if ((unsigned)yy < 128u) {
#pragma unroll
                    for (int kx = 0; kx < 3; kx++) {
                        int xx = ox + kx - 1;
                        if ((unsigned)xx < 128u) {
                            float iv = ib[yy * 128 + xx];
                            float2 a; a.x = iv; a.y = iv;
                            a0 = ffma2(a, w0[ky * 3 + kx], a0);
                            a1 = ffma2(a, w1[ky * 3 + kx], a1);
                        }
                    }
                }
            }
            m0.x = fmaxf(m0.x, a0.x); m0.y = fmaxf(m0.y, a0.y);
            m1.x = fmaxf(m1.x, a1.x); m1.y = fmaxf(m1.y, a1.y);
        }
    }
    float4 o; o.x = m0.x; o.y = m0.y; o.z = m1.x; o.w = m1.y;
    *(float4*)(g_pool1 + ((b * 4096 + y * 64 + x) * 32 + cq * 4)) = o;
}

// ---------------- K2: conv2 (3x3x32->64, SAME) + relu + fused tile-reduce ----
#define IN_PLANE 360                     // 18 rows x 20 floats; 1440B (16B-mult)
#define CONV2_SMEM (32 * IN_PLANE * 4)   // 46080B
__global__ void __launch_bounds__(256, 2) k_conv2(const float* __restrict__ w,
                                                  const float* __restrict__ bias) {
    extern __shared__ __align__(16) float sm[];
    float* in_s = sm;                    // [32][360]

    int b  = blockIdx.x >> 4;
    int t  = blockIdx.x & 15;
    int ty = t >> 2, tx = t & 3;
    int tid = threadIdx.x;

    for (int i = tid; i < 32 * 18 * 18; i += 256) {
        int ci = i & 31;
        int rest = i >> 5;
        int sy = rest / 18, sx = rest - sy * 18;
        int gy = ty * 16 + sy - 1, gx = tx * 16 + sx - 1;
        float v = 0.f;
        if ((unsigned)gy < 64u && (unsigned)gx < 64u)
            v = g_pool1[((b * 64 + gy) * 64 + gx) * 32 + ci];
        in_s[ci * IN_PLANE + sy * 20 + sx] = v;
    }
    __syncthreads();

    int cg = tid & 7;          // co = cg*8 + [0..8)
    int pg = tid >> 3;         // 0..31 (row-major pixel groups in tile)
    int r  = pg >> 1;          // tile row 0..15
    int x0 = (pg & 1) * 8;     // half-row start (16B-aligned loads)

    float2 acc[8][4];
    {
        const float2* bp = (const float2*)(bias + cg * 8);
#pragma unroll
        for (int jj = 0; jj < 4; jj++) {
            float2 bv = bp[jj];
#pragma unroll
            for (int j = 0; j < 8; j++) acc[j][jj] = bv;
        }
    }

#pragma unroll 1
    for (int ky = 0; ky < 3; ky++) {
        const float* rowb = in_s + (r + ky) * 20 + x0;
        const float4* wb  = (const float4*)(w + (ky * 3) * 2048 + cg * 8);
#pragma unroll 4
        for (int ci = 0; ci < 32; ci++) {
            const float4* ip = (const float4*)(rowb + ci * IN_PLANE);
            float4 fa = ip[0], fb = ip[1], fc = ip[2];
            float f[12] = {fa.x, fa.y, fa.z, fa.w,
                           fb.x, fb.y, fb.z, fb.w,
                           fc.x, fc.y, fc.z, fc.w};
#pragma unroll
            for (int kx = 0; kx < 3; kx++) {
                const float4* wp = wb + (kx * 2048 + ci * 64) / 4;
                float4 wa = __ldg(wp);
                float4 wc = __ldg(wp + 1);
                float2 wv0; wv0.x = wa.x; wv0.y = wa.y;
                float2 wv1; wv1.x = wa.z; wv1.y = wa.w;
                float2 wv2; wv2.x = wc.x; wv2.y = wc.y;
                float2 wv3; wv3.x = wc.z; wv3.y = wc.w;
#pragma unroll
                for (int j = 0; j < 8; j++) {
                    float iv = f[j + kx];
                    float2 a; a.x = iv; a.y = iv;
                    acc[j][0] = ffma2(a, wv0, acc[j][0]);
                    acc[j][1] = ffma2(a, wv1, acc[j][1]);
                    acc[j][2] = ffma2(a, wv2, acc[j][2]);
                    acc[j][3] = ffma2(a, wv3, acc[j][3]);
                }
            }
        }
    }

    int gy  = ty * 16 + r;
    int gxb = tx * 16 + x0;
#pragma unroll
    for (int j = 0; j < 8; j++) {
#pragma unroll
        for (int jj = 0; jj < 4; jj++) {
            acc[j][jj].x = fmaxf(acc[j][jj].x, 0.f);
            acc[j][jj].y = fmaxf(acc[j][jj].y, 0.f);
        }
        *(float2*)(g_conv2 + ((b * 64 + gy) * 64 + gxb + j) * 64 + cg * 8 + 0) = acc[j][0];
        *(float2*)(g_conv2 + ((b * 64 + gy) * 64 + gxb + j) * 64 + cg * 8 + 2) = acc[j][1];
        *(float2*)(g_conv2 + ((b * 64 + gy) * 64 + gxb + j) * 64 + cg * 8 + 4) = acc[j][2];
        *(float2*)(g_conv2 + ((b * 64 + gy) * 64 + gxb + j) * 64 + cg * 8 + 6) = acc[j][3];
    }

    // ---- fused per-tile reduction (max / first-argmax / sum per channel) ----
    __syncthreads();
    float* rmax = in_s;               // [32 pg][64 c]
    float* rsum = in_s + 2048;
    int*   ridx = (int*)(in_s + 4096);

#pragma unroll
    for (int jj = 0; jj < 4; jj++) {
        float m0 = -1.f, m1 = -1.f, s0 = 0.f, s1 = 0.f;
        int i0 = 0, i1 = 0;
#pragma unroll
        for (int j = 0; j < 8; j++) {       // j increasing = pixel order
            float v0 = acc[j][jj].x, v1 = acc[j][jj].y;
            s0 += v0; s1 += v1;
            if (v0 > m0) { m0 = v0; i0 = j; }
            if (v1 > m1) { m1 = v1; i1 = j; }
        }
        int base = gy * 64 + gxb;
        int c0 = cg * 8 + 2 * jj;
        rmax[pg * 64 + c0] = m0;     rmax[pg * 64 + c0 + 1] = m1;
        rsum[pg * 64 + c0] = s0;     rsum[pg * 64 + c0 + 1] = s1;
        ridx[pg * 64 + c0] = base + i0; ridx[pg * 64 + c0 + 1] = base + i1;
    }
    __syncthreads();

    if (tid < 64) {
        int c = tid;
        float B = -1.f, S = 0.f;
        int I = 0x7FFFFFFF;
#pragma unroll
        for (int g = 0; g < 32; g++) {
            float v = rmax[g * 64 + c];
            int   i = ridx[g * 64 + c];
            S += rsum[g * 64 + c];
            if (v > B || (v == B && i < I)) { B = v; I = i; }
        }
        int o = (b * 16 + t) * 64 + c;
        g_pmax[o] = B; g_pidx[o] = I; g_psum[o] = S;
    }
}

// ---------------- K3: mask+relu+pool, amax reduced per-block (2048 CTAs) -----
__global__ void __launch_bounds__(256) k_maskpool(float* __restrict__ outp) {
    int blk = blockIdx.x;            // 2048; 64 blocks per batch
    int tid = threadIdx.x;
    int b   = blk >> 6;

    __shared__ float smu[64][2];     // per-channel (mux, muy)
    if (tid < 64) {
        int c = tid;
        float B = -1.f;
        int I = 0x7FFFFFFF;
#pragma unroll
        for (int t = 0; t < 16; t++) {
            int o = (b * 16 + t) * 64 + c;
            float v = g_pmax[o];
            int   i = g_pidx[o];
            if (v > B || (v == B && i < I)) { B = v; I = i; }
        }
        smu[c][0] = (float)(I >> 6) * (1.f / 31.5f) - 1.f;
        smu[c][1] = (float)(I & 63) * (1.f / 31.5f) - 1.f;
    }
    __syncthreads();

    int idx = blk * 256 + tid;       // quad index over 524288
    int cq = idx & 15;
    int px = (idx >> 4) & 31;
    int py = (idx >> 9) & 31;

    int c0 = cq * 4;
    float mux0 = smu[c0][0],     muy0 = smu[c0][1];
    float mux1 = smu[c0 + 1][0], muy1 = smu[c0 + 1][1];
    float mux2 = smu[c0 + 2][0], muy2 = smu[c0 + 2][1];
    float mux3 = smu[c0 + 3][0], muy3 = smu[c0 + 3][1];

    float4 m = make_float4(0.f, 0.f, 0.f, 0.f);
#pragma unroll
    for (int sy = 0; sy < 2; sy++) {
#pragma unroll
        for (int sx = 0; sx < 2; sx++) {
            int yy = 2 * py + sy, xx = 2 * px + sx;
            float ly = (float)yy * (2.f / 63.f) - 1.f;
            float lx = (float)xx * (2.f / 63.f) - 1.f;
            float4 v = *(const float4*)(g_conv2 + ((b * 64 + yy) * 64 + xx) * 64 + c0);
            float k0 = fmaxf(1.f - 0.5f * (fabsf(ly - mux0) + fabsf(lx - muy0)), -1.f);
            float k1 = fmaxf(1.f - 0.5f * (fabsf(ly - mux1) + fabsf(lx - muy1)), -1.f);
            float k2 = fmaxf(1.f - 0.5f * (fabsf(ly - mux2) + fabsf(lx - muy2)), -1.f);
            float k3 = fmaxf(1.f - 0.5f * (fabsf(ly - mux3) + fabsf(lx - muy3)), -1.f);
            m.x = fmaxf(m.x, v.x * k0);
            m.y = fmaxf(m.y, v.y * k1);
            m.z = fmaxf(m.z, v.z * k2);
            m.w = fmaxf(m.w, v.w * k3);
        }
    }
    ((float4*)outp)[idx] = m;
}

// ---------------- K4: dense1 split-K, 2n x 16b per thread, occ=4 -------------
// M=32, N=1024, K=65536. grid (4 n-chunks of 256, 128 k-splits), 256 threads.
// Thread (nq 0..127, bh 0..1): n = chunk*256 + nq*2 (+0,1), batches bh*16..+15.
// Per k: 1 LDG.64 (2 w) + 4 broadcast LDS.128 + 16 FFMA2. 4 CTAs/SM.
#define XS_STRIDE 36
__global__ void __launch_bounds__(256, 4) k_dense1(const float* __restrict__ x,
                                                   const float* __restrict__ w) {
    __shared__ __align__(16) float xs[128 * XS_STRIDE];   // [kk][b]
    int tid = threadIdx.x;
    int nq  = tid & 127;
    int bh  = tid >> 7;              // batch half
    int n0 = blockIdx.x * 256 + nq * 2;
    int kbase = blockIdx.y * 512;

    float2 a0[8], a1[8];             // [bpair] for n0, n0+1
#pragma unroll
    for (int p = 0; p < 8; p++) {
        a0[p] = make_float2(0.f, 0.f);
        a1[p] = make_float2(0.f, 0.f);
    }

    for (int t = 0; t < 512; t += 128) {
        __syncthreads();
        for (int i = tid; i < 4096; i += 256) {
            int kk = i & 127, bb = i >> 7;
            xs[kk * XS_STRIDE + bb] = x[bb * 65536 + kbase + t + kk];
        }
        __syncthreads();
        const float* wrow = w + (size_t)(kbase + t) * 1024 + n0;
#pragma unroll 8
        for (int kk = 0; kk < 128; kk++) {
            float2 wv = *(const float2*)(wrow + (size_t)kk * 1024);
            float2 w0; w0.x = wv.x; w0.y = wv.x;
            float2 w1; w1.x = wv.y; w1.y = wv.y;
            const float4* xp = (const float4*)(xs + kk * XS_STRIDE + bh * 16);
#pragma unroll
            for (int q = 0; q < 4; q++) {
                float4 xv = xp[q];                  // batches bh*16+4q..+3
                float2 lo; lo.x = xv.x; lo.y = xv.y;
                float2 hi; hi.x = xv.z; hi.y = xv.w;
                a0[2 * q]     = ffma2(lo, w0, a0[2 * q]);
                a0[2 * q + 1] = ffma2(hi, w0, a0[2 * q + 1]);
                a1[2 * q]     = ffma2(lo, w1, a1[2 * q]);
                a1[2 * q + 1] = ffma2(hi, w1, a1[2 * q + 1]);
            }
        }
    }
    float* p = g_part + (size_t)blockIdx.y * 32 * 1024;
#pragma unroll
    for (int q = 0; q < 8; q++) {
        int b0 = bh * 16 + 2 * q;
        p[b0 * 1024 + n0]           = a0[q].x;
        p[(b0 + 1) * 1024 + n0]     = a0[q].y;
        p[b0 * 1024 + n0 + 1]       = a1[q].x;
        p[(b0 + 1) * 1024 + n0 + 1] = a1[q].y;
    }
}

// ---------------- K5: segment-mean -> argmax category per filter -------------
__global__ void k_filters(const int* __restrict__ lab32,
                          float* __restrict__ outf) {
    __shared__ float sc[2048];      // csum[b][c]
    __shared__ float mean[10][64];
    __shared__ int lbl[32];
    int tid = threadIdx.x;

    for (int i = tid; i < 2048; i += 640) {
        int b = i >> 6, c = i & 63;
        float s = 0.f;
#pragma unroll
        for (int t = 0; t < 16; t++) s += g_psum[(b * 16 + t) * 64 + c];
        sc[i] = s;
    }
    if (tid == 0) {
        bool is64 = true;
        for (int i = 1; i < 32; i += 2)
            if (lab32[i] != 0) { is64 = false; break; }
        if (is64) {
            const long long* l64 = (const long long*)lab32;
            for (int b = 0; b < 32; b++) lbl[b] = (int)l64[b];
        } else {
            for (int b = 0; b < 32; b++) lbl[b] = lab32[b];
        }
    }
    __syncthreads();

    {
        int cat = tid / 64, c = tid & 63;
        float s = 0.f; int ct = 0;
        for (int b = 0; b < 32; b++) {
            if (lbl[b] == cat) { s += sc[b * 64 + c]; ct++; }
        }
        mean[cat][c] = s / (float)ct;         // ct==0 -> NaN (numpy: NaN wins)
    }
    __syncthreads();

    if (tid < 64) {
        float best = 0.f;
        int bi = 0;
        bool have = false, bnan = false;
        for (int cat = 0; cat < 10; cat++) {
            float v = mean[cat][tid];
            bool vn = isnan(v);
            if (!bnan && (vn || !have || v > best)) {
                best = v; bi = cat; bnan = vn; have = true;
            }
        }
        outf[tid] = (float)bi;
    }
}

// ---------------- K6: reduce partials + bias + relu --------------------------
__global__ void k_dense1_fin(const float* __restrict__ bias) {
    int idx = blockIdx.x * 256 + threadIdx.x;   // 32*1024
    int n = idx & 1023, b = idx >> 10;
    float s = 0.f;
#pragma unroll 16
    for (int ks = 0; ks < 128; ks++) s += g_part[(ks * 32 + b) * 1024 + n];
    g_hidden[idx] = fmaxf(s + bias[n], 0.f);
}

// ---------------- K7: dense2 -> logits (k-parallel + smem tree) --------------
__global__ void k_dense2(const float* __restrict__ w,
                         const float* __restrict__ bias,
                         float* __restrict__ logits) {
    int b = blockIdx.x;            // 32
    int tid = threadIdx.x;         // 256
    float acc[10];
#pragma unroll
    for (int j = 0; j < 10; j++) acc[j] = 0.f;
    const float* h = g_hidden + b * 1024;
#pragma unroll
    for (int t = 0; t < 4; t++) {
        int k = t * 256 + tid;
        float hv = h[k];
        const float* wr = w + k * 10;
#pragma unroll
        for (int j = 0; j < 10; j++) acc[j] = fmaf(hv, wr[j], acc[j]);
    }
    __shared__ float s[256 * 10];
#pragma unroll
    for (int j = 0; j < 10; j++) s[tid * 10 + j] = acc[j];
    __syncthreads();
    for (int off = 128; off > 0; off >>= 1) {
        if (tid < off) {
#pragma unroll
            for (int j = 0; j < 10; j++)
                s[tid * 10 + j] += s[(tid + off) * 10 + j];
        }
        __syncthreads();
    }
    if (tid < 10) logits[b * 10 + tid] = s[tid] + bias[tid];
}

// ---------------- launcher ---------------------------------------------------
extern "C" void kernel_launch(void* const* d_in, const int* in_sizes, int n_in,
                              void* d_out, int out_size) {
    const float* inputs = (const float*)d_in[0];
    const int*   labels = (const int*)d_in[1];   // dtype resolved on-device
    const float* c1w = (const float*)d_in[2];
    const float* c1b = (const float*)d_in[3];
    const float* c2w = (const float*)d_in[4];
    const float* c2b = (const float*)d_in[5];
    const float* d1w = (const float*)d_in[6];
    const float* d1b = (const float*)d_in[7];
    const float* d2w = (const float*)d_in[8];
    const float* d2b = (const float*)d_in[9];

    float* out = (float*)d_out;
    float* out_logits = out;                       // (32,10)
    float* out_pool   = out + 320;                 // (32,32,32,64)
    float* out_filt   = out + 320 + 2097152;       // (64,)

    k_conv1_pool<<<4096, 256>>>(inputs, c1w, c1b);
    k_conv2<<<512, 256, CONV2_SMEM>>>(c2w, c2b);
    k_maskpool<<<2048, 256>>>(out_pool);
    k_dense1<<<dim3(4, 128), 256>>>(out_pool, d1w);   // launch idx 3 -> profiled
    k_filters<<<1, 640>>>(labels, out_filt);
    k_dense1_fin<<<128, 256>>>(d1b);
    k_dense2<<<32, 256>>>(d2w, d2b, out_logits);
}

// round 13
// speedup vs baseline: 1.1338x; 1.1338x over previous
#include <cuda_runtime.h>
#include <cstdint>

typedef unsigned long long ull_t;

// packed fp32x2 FMA (sm_100+): two independent fp32 FMAs, bit-exact vs scalar
__device__ __forceinline__ float2 ffma2(float2 a, float2 b, float2 c) {
    float2 d;
    asm("fma.rn.f32x2 %0, %1, %2, %3;"
        : "=l"(reinterpret_cast<ull_t&>(d))
        : "l"(reinterpret_cast<ull_t&>(a)),
          "l"(reinterpret_cast<ull_t&>(b)),
          "l"(reinterpret_cast<ull_t&>(c)));
    return d;
}

// ---------------- scratch (device globals; no allocations allowed) ----------
__device__ float g_pool1[32 * 64 * 64 * 32];     // conv1+pool output
__device__ float g_conv2[32 * 64 * 64 * 64];     // conv2+relu output
__device__ float g_pmax[32 * 16 * 64];           // per (b,tile,c) partial max
__device__ int   g_pidx[32 * 16 * 64];           // per (b,tile,c) partial argmax
__device__ float g_psum[32 * 16 * 64];           // per (b,tile,c) partial sum
__device__ float g_part[128 * 32 * 1024];        // dense1 split-K partials
__device__ float g_hidden[32 * 1024];            // dense1 output (post relu)

// ---------------- K1: conv1 (3x3x1->32) + relu + 2x2 maxpool, 4ch/thread ----
__global__ void k_conv1_pool(const float* __restrict__ in,
                             const float* __restrict__ w,
                             const float* __restrict__ bias) {
    int idx = blockIdx.x * 256 + threadIdx.x;     // 32*64*64*8 = 1,048,576
    int cq = idx & 7;                             // channel quad: c = cq*4..+3
    int x = (idx >> 3) & 63;
    int y = (idx >> 9) & 63;
    int b = idx >> 15;

    float2 w0[9], w1[9];
#pragma unroll
    for (int i = 0; i < 9; i++) {
        float4 wv = *(const float4*)(w + i * 32 + cq * 4);
        w0[i].x = wv.x; w0[i].y = wv.y;
        w1[i].x = wv.z; w1[i].y = wv.w;
    }
    float4 bv = *(const float4*)(bias + cq * 4);
    float2 b0; b0.x = bv.x; b0.y = bv.y;
    float2 b1; b1.x = bv.z; b1.y = bv.w;
    const float* ib = in + b * 16384;

    float2 m0 = make_float2(0.f, 0.f), m1 = make_float2(0.f, 0.f);
#pragma unroll
    for (int sy = 0; sy < 2; sy++) {
#pragma unroll
        for (int sx = 0; sx < 2; sx++) {
            int oy = 2 * y + sy, ox = 2 * x + sx;
            float2 a0 = b0, a1 = b1;
#pragma unroll
            for (int ky = 0; ky < 3; ky++) {
                int yy = oy + ky - 1;
                if ((unsigned)yy < 128u) {
#pragma unroll
                    for (int kx = 0; kx < 3; kx++) {
                        int xx = ox + kx - 1;
                        if ((unsigned)xx < 128u) {
                            float iv = ib[yy * 128 + xx];
                            float2 a; a.x = iv; a.y = iv;
                            a0 = ffma2(a, w0[ky * 3 + kx], a0);
                            a1 = ffma2(a, w1[ky * 3 + kx], a1);
                        }
                    }
                }
            }
            m0.x = fmaxf(m0.x, a0.x); m0.y = fmaxf(m0.y, a0.y);
            m1.x = fmaxf(m1.x, a1.x); m1.y = fmaxf(m1.y, a1.y);
        }
    }
    float4 o; o.x = m0.x; o.y = m0.y; o.z = m1.x; o.w = m1.y;
    *(float4*)(g_pool1 + ((b * 4096 + y * 64 + x) * 32 + cq * 4)) = o;
}

// ---------------- K2: conv2 (3x3x32->64, SAME) + relu + fused tile-reduce ----
#define IN_PLANE 360                     // 18 rows x 20 floats; 1440B (16B-mult)
#define CONV2_SMEM (32 * IN_PLANE * 4)   // 46080B
__global__ void __launch_bounds__(256, 2) k_conv2(const float* __restrict__ w,
                                                  const float* __restrict__ bias) {
    extern __shared__ __align__(16) float sm[];
    float* in_s = sm;                    // [32][360]

    int b  = blockIdx.x >> 4;
    int t  = blockIdx.x & 15;
    int ty = t >> 2, tx = t & 3;
    int tid = threadIdx.x;

    for (int i = tid; i < 32 * 18 * 18; i += 256) {
        int ci = i & 31;
        int rest = i >> 5;
        int sy = rest / 18, sx = rest - sy * 18;
        int gy = ty * 16 + sy - 1, gx = tx * 16 + sx - 1;
        float v = 0.f;
        if ((unsigned)gy < 64u && (unsigned)gx < 64u)
            v = g_pool1[((b * 64 + gy) * 64 + gx) * 32 + ci];
        in_s[ci * IN_PLANE + sy * 20 + sx] = v;
    }
    __syncthreads();

    int cg = tid & 7;          // co = cg*8 + [0..8)
    int pg = tid >> 3;         // 0..31 (row-major pixel groups in tile)
    int r  = pg >> 1;          // tile row 0..15
    int x0 = (pg & 1) * 8;     // half-row start (16B-aligned loads)

    float2 acc[8][4];
    {
        const float2* bp = (const float2*)(bias + cg * 8);
#pragma unroll
        for (int jj = 0; jj < 4; jj++) {
            float2 bv = bp[jj];
#pragma unroll
            for (int j = 0; j < 8; j++) acc[j][jj] = bv;
        }
    }

#pragma unroll 1
    for (int ky = 0; ky < 3; ky++) {
        const float* rowb = in_s + (r + ky) * 20 + x0;
        const float4* wb  = (const float4*)(w + (ky * 3) * 2048 + cg * 8);
#pragma unroll 4
        for (int ci = 0; ci < 32; ci++) {
            const float4* ip = (const float4*)(rowb + ci * IN_PLANE);
            float4 fa = ip[0], fb = ip[1], fc = ip[2];
            float f[12] = {fa.x, fa.y, fa.z, fa.w,
                           fb.x, fb.y, fb.z, fb.w,
                           fc.x, fc.y, fc.z, fc.w};
#pragma unroll
            for (int kx = 0; kx < 3; kx++) {
                const float4* wp = wb + (kx * 2048 + ci * 64) / 4;
                float4 wa = __ldg(wp);
                float4 wc = __ldg(wp + 1);
                float2 wv0; wv0.x = wa.x; wv0.y = wa.y;
                float2 wv1; wv1.x = wa.z; wv1.y = wa.w;
                float2 wv2; wv2.x = wc.x; wv2.y = wc.y;
                float2 wv3; wv3.x = wc.z; wv3.y = wc.w;
#pragma unroll
                for (int j = 0; j < 8; j++) {
                    float iv = f[j + kx];
                    float2 a; a.x = iv; a.y = iv;
                    acc[j][0] = ffma2(a, wv0, acc[j][0]);
                    acc[j][1] = ffma2(a, wv1, acc[j][1]);
                    acc[j][2] = ffma2(a, wv2, acc[j][2]);
                    acc[j][3] = ffma2(a, wv3, acc[j][3]);
                }
            }
        }
    }

    int gy  = ty * 16 + r;
    int gxb = tx * 16 + x0;
#pragma unroll
    for (int j = 0; j < 8; j++) {
#pragma unroll
        for (int jj = 0; jj < 4; jj++) {
            acc[j][jj].x = fmaxf(acc[j][jj].x, 0.f);
            acc[j][jj].y = fmaxf(acc[j][jj].y, 0.f);
        }
        *(float2*)(g_conv2 + ((b * 64 + gy) * 64 + gxb + j) * 64 + cg * 8 + 0) = acc[j][0];
        *(float2*)(g_conv2 + ((b * 64 + gy) * 64 + gxb + j) * 64 + cg * 8 + 2) = acc[j][1];
        *(float2*)(g_conv2 + ((b * 64 + gy) * 64 + gxb + j) * 64 + cg * 8 + 4) = acc[j][2];
        *(float2*)(g_conv2 + ((b * 64 + gy) * 64 + gxb + j) * 64 + cg * 8 + 6) = acc[j][3];
    }

    // ---- fused per-tile reduction (max / first-argmax / sum per channel) ----
    __syncthreads();
    float* rmax = in_s;               // [32 pg][64 c]
    float* rsum = in_s + 2048;
    int*   ridx = (int*)(in_s + 4096);

#pragma unroll
    for (int jj = 0; jj < 4; jj++) {
        float m0 = -1.f, m1 = -1.f, s0 = 0.f, s1 = 0.f;
        int i0 = 0, i1 = 0;
#pragma unroll
        for (int j = 0; j < 8; j++) {       // j increasing = pixel order
            float v0 = acc[j][jj].x, v1 = acc[j][jj].y;
            s0 += v0; s1 += v1;
            if (v0 > m0) { m0 = v0; i0 = j; }
            if (v1 > m1) { m1 = v1; i1 = j; }
        }
        int base = gy * 64 + gxb;
        int c0 = cg * 8 + 2 * jj;
        rmax[pg * 64 + c0] = m0;     rmax[pg * 64 + c0 + 1] = m1;
        rsum[pg * 64 + c0] = s0;     rsum[pg * 64 + c0 + 1] = s1;
        ridx[pg * 64 + c0] = base + i0; ridx[pg * 64 + c0 + 1] = base + i1;
    }
    __syncthreads();

    if (tid < 64) {
        int c = tid;
        float B = -1.f, S = 0.f;
        int I = 0x7FFFFFFF;
#pragma unroll
        for (int g = 0; g < 32; g++) {
            float v = rmax[g * 64 + c];
            int   i = ridx[g * 64 + c];
            S += rsum[g * 64 + c];
            if (v > B || (v == B && i < I)) { B = v; I = i; }
        }
        int o = (b * 16 + t) * 64 + c;
        g_pmax[o] = B; g_pidx[o] = I; g_psum[o] = S;
    }
}

// ---------------- K3: mask+relu+pool, amax reduced per-block (2048 CTAs) -----
__global__ void __launch_bounds__(256) k_maskpool(float* __restrict__ outp) {
    int blk = blockIdx.x;            // 2048; 64 blocks per batch
    int tid = threadIdx.x;
    int b   = blk >> 6;

    __shared__ float smu[64][2];     // per-channel (mux, muy)
    if (tid < 64) {
        int c = tid;
        float B = -1.f;
        int I = 0x7FFFFFFF;
#pragma unroll
        for (int t = 0; t < 16; t++) {
            int o = (b * 16 + t) * 64 + c;
            float v = g_pmax[o];
            int   i = g_pidx[o];
            if (v > B || (v == B && i < I)) { B = v; I = i; }
        }
        smu[c][0] = (float)(I >> 6) * (1.f / 31.5f) - 1.f;
        smu[c][1] = (float)(I & 63) * (1.f / 31.5f) - 1.f;
    }
    __syncthreads();

    int idx = blk * 256 + tid;       // quad index over 524288
    int cq = idx & 15;
    int px = (idx >> 4) & 31;
    int py = (idx >> 9) & 31;

    int c0 = cq * 4;
    float mux0 = smu[c0][0],     muy0 = smu[c0][1];
    float mux1 = smu[c0 + 1][0], muy1 = smu[c0 + 1][1];
    float mux2 = smu[c0 + 2][0], muy2 = smu[c0 + 2][1];
    float mux3 = smu[c0 + 3][0], muy3 = smu[c0 + 3][1];

    float4 m = make_float4(0.f, 0.f, 0.f, 0.f);
#pragma unroll
    for (int sy = 0; sy < 2; sy++) {
#pragma unroll
        for (int sx = 0; sx < 2; sx++) {
            int yy = 2 * py + sy, xx = 2 * px + sx;
            float ly = (float)yy * (2.f / 63.f) - 1.f;
            float lx = (float)xx * (2.f / 63.f) - 1.f;
            float4 v = *(const float4*)(g_conv2 + ((b * 64 + yy) * 64 + xx) * 64 + c0);
            float k0 = fmaxf(1.f - 0.5f * (fabsf(ly - mux0) + fabsf(lx - muy0)), -1.f);
            float k1 = fmaxf(1.f - 0.5f * (fabsf(ly - mux1) + fabsf(lx - muy1)), -1.f);
            float k2 = fmaxf(1.f - 0.5f * (fabsf(ly - mux2) + fabsf(lx - muy2)), -1.f);
            float k3 = fmaxf(1.f - 0.5f * (fabsf(ly - mux3) + fabsf(lx - muy3)), -1.f);
            m.x = fmaxf(m.x, v.x * k0);
            m.y = fmaxf(m.y, v.y * k1);
            m.z = fmaxf(m.z, v.z * k2);
            m.w = fmaxf(m.w, v.w * k3);
        }
    }
    ((float4*)outp)[idx] = m;
}

// ---------------- K4: dense1 split-K, 2n x 32b per thread, unroll 8 ----------
// M=32, N=1024, K=65536. grid (2 n-halves, 128 k-splits), 256 threads.
// Per k: 1 LDG.64 (w pair) + 8 broadcast LDS.128 + 32 FFMA2. unroll 8 so
// ptxas front-batches 8 independent w-LDGs (MLP 8 -> DRAM latency hidden).
#define XS_STRIDE 36
__global__ void __launch_bounds__(256, 2) k_dense1(const float* __restrict__ x,
                                                   const float* __restrict__ w) {
    __shared__ __align__(16) float xs[128 * XS_STRIDE];   // [kk][b]
    int tid = threadIdx.x;
    int n0 = blockIdx.x * 512 + tid * 2;
    int kbase = blockIdx.y * 512;

    float2 a0[16], a1[16];
#pragma unroll
    for (int i = 0; i < 16; i++) {
        a0[i] = make_float2(0.f, 0.f);
        a1[i] = make_float2(0.f, 0.f);
    }

    for (int t = 0; t < 512; t += 128) {
        __syncthreads();
        for (int i = tid; i < 4096; i += 256) {
            int kk = i & 127, bb = i >> 7;
            xs[kk * XS_STRIDE + bb] = x[bb * 65536 + kbase + t + kk];
        }
        __syncthreads();
        const float* wrow = w + (size_t)(kbase + t) * 1024 + n0;
#pragma unroll 8
        for (int kk = 0; kk < 128; kk++) {
            float2 wv = *(const float2*)(wrow + (size_t)kk * 1024);
            float2 w0; w0.x = wv.x; w0.y = wv.x;
            float2 w1; w1.x = wv.y; w1.y = wv.y;
            const float4* xp = (const float4*)(xs + kk * XS_STRIDE);
#pragma unroll
            for (int q = 0; q < 8; q++) {
                float4 xv = xp[q];                    // batches 4q..4q+3
                float2 lo; lo.x = xv.x; lo.y = xv.y;
                float2 hi; hi.x = xv.z; hi.y = xv.w;
                a0[2 * q]     = ffma2(lo, w0, a0[2 * q]);
                a0[2 * q + 1] = ffma2(hi, w0, a0[2 * q + 1]);
                a1[2 * q]     = ffma2(lo, w1, a1[2 * q]);
                a1[2 * q + 1] = ffma2(hi, w1, a1[2 * q + 1]);
            }
        }
    }
    float* p = g_part + (size_t)blockIdx.y * 32 * 1024;
#pragma unroll
    for (int bb = 0; bb < 16; bb++) {
        p[(2 * bb) * 1024 + n0]         = a0[bb].x;
        p[(2 * bb + 1) * 1024 + n0]     = a0[bb].y;
        p[(2 * bb) * 1024 + n0 + 1]     = a1[bb].x;
        p[(2 * bb + 1) * 1024 + n0 + 1] = a1[bb].y;
    }
}

// ---------------- K5: segment-mean -> argmax category per filter -------------
__global__ void k_filters(const int* __restrict__ lab32,
                          float* __restrict__ outf) {
    __shared__ float sc[2048];      // csum[b][c]
    __shared__ float mean[10][64];
    __shared__ int lbl[32];
    int tid = threadIdx.x;

    for (int i = tid; i < 2048; i += 640) {
        int b = i >> 6, c = i & 63;
        float s = 0.f;
#pragma unroll
        for (int t = 0; t < 16; t++) s += g_psum[(b * 16 + t) * 64 + c];
        sc[i] = s;
    }
    if (tid == 0) {
        bool is64 = true;
        for (int i = 1; i < 32; i += 2)
            if (lab32[i] != 0) { is64 = false; break; }
        if (is64) {
            const long long* l64 = (const long long*)lab32;
            for (int b = 0; b < 32; b++) lbl[b] = (int)l64[b];
        } else {
            for (int b = 0; b < 32; b++) lbl[b] = lab32[b];
        }
    }
    __syncthreads();

    {
        int cat = tid / 64, c = tid & 63;
        float s = 0.f; int ct = 0;
        for (int b = 0; b < 32; b++) {
            if (lbl[b] == cat) { s += sc[b * 64 + c]; ct++; }
        }
        mean[cat][c] = s / (float)ct;         // ct==0 -> NaN (numpy: NaN wins)
    }
    __syncthreads();

    if (tid < 64) {
        float best = 0.f;
        int bi = 0;
        bool have = false, bnan = false;
        for (int cat = 0; cat < 10; cat++) {
            float v = mean[cat][tid];
            bool vn = isnan(v);
            if (!bnan && (vn || !have || v > best)) {
                best = v; bi = cat; bnan = vn; have = true;
            }
        }
        outf[tid] = (float)bi;
    }
}

// ---------------- K6: reduce partials + bias + relu --------------------------
__global__ void k_dense1_fin(const float* __restrict__ bias) {
    int idx = blockIdx.x * 256 + threadIdx.x;   // 32*1024
    int n = idx & 1023, b = idx >> 10;
    float s = 0.f;
#pragma unroll 16
    for (int ks = 0; ks < 128; ks++) s += g_part[(ks * 32 + b) * 1024 + n];
    g_hidden[idx] = fmaxf(s + bias[n], 0.f);
}

// ---------------- K7: dense2 -> logits (k-parallel + smem tree) --------------
__global__ void k_dense2(const float* __restrict__ w,
                         const float* __restrict__ bias,
                         float* __restrict__ logits) {
    int b = blockIdx.x;            // 32
    int tid = threadIdx.x;         // 256
    float acc[10];
#pragma unroll
    for (int j = 0; j < 10; j++) acc[j] = 0.f;
    const float* h = g_hidden + b * 1024;
#pragma unroll
    for (int t = 0; t < 4; t++) {
        int k = t * 256 + tid;
        float hv = h[k];
        const float* wr = w + k * 10;
#pragma unroll
        for (int j = 0; j < 10; j++) acc[j] = fmaf(hv, wr[j], acc[j]);
    }
    __shared__ float s[256 * 10];
#pragma unroll
    for (int j = 0; j < 10; j++) s[tid * 10 + j] = acc[j];
    __syncthreads();
    for (int off = 128; off > 0; off >>= 1) {
        if (tid < off) {
#pragma unroll
            for (int j = 0; j < 10; j++)
                s[tid * 10 + j] += s[(tid + off) * 10 + j];
        }
        __syncthreads();
    }
    if (tid < 10) logits[b * 10 + tid] = s[tid] + bias[tid];
}

// ---------------- launcher ---------------------------------------------------
extern "C" void kernel_launch(void* const* d_in, const int* in_sizes, int n_in,
                              void* d_out, int out_size) {
    const float* inputs = (const float*)d_in[0];
    const int*   labels = (const int*)d_in[1];   // dtype resolved on-device
    const float* c1w = (const float*)d_in[2];
    const float* c1b = (const float*)d_in[3];
    const float* c2w = (const float*)d_in[4];
    const float* c2b = (const float*)d_in[5];
    const float* d1w = (const float*)d_in[6];
    const float* d1b = (const float*)d_in[7];
    const float* d2w = (const float*)d_in[8];
    const float* d2b = (const float*)d_in[9];

    float* out = (float*)d_out;
    float* out_logits = out;                       // (32,10)
    float* out_pool   = out + 320;                 // (32,32,32,64)
    float* out_filt   = out + 320 + 2097152;       // (64,)

    k_conv1_pool<<<4096, 256>>>(inputs, c1w, c1b);
    k_conv2<<<512, 256, CONV2_SMEM>>>(c2w, c2b);
    k_maskpool<<<2048, 256>>>(out_pool);
    k_dense1<<<dim3(2, 128), 256>>>(out_pool, d1w);   // launch idx 3 -> profiled
    k_filters<<<1, 640>>>(labels, out_filt);
    k_dense1_fin<<<128, 256>>>(d1b);
    k_dense2<<<32, 256>>>(d2w, d2b, out_logits);
}

// round 14
// speedup vs baseline: 1.1620x; 1.0249x over previous
#include <cuda_runtime.h>
#include <cstdint>

typedef unsigned long long ull_t;

// packed fp32x2 FMA (sm_100+): two independent fp32 FMAs, bit-exact vs scalar
__device__ __forceinline__ float2 ffma2(float2 a, float2 b, float2 c) {
    float2 d;
    asm("fma.rn.f32x2 %0, %1, %2, %3;"
        : "=l"(reinterpret_cast<ull_t&>(d))
        : "l"(reinterpret_cast<ull_t&>(a)),
          "l"(reinterpret_cast<ull_t&>(b)),
          "l"(reinterpret_cast<ull_t&>(c)));
    return d;
}

// ---------------- scratch (device globals; no allocations allowed) ----------
__device__ float g_pool1[32 * 64 * 64 * 32];     // conv1+pool output
__device__ float g_conv2[32 * 64 * 64 * 64];     // conv2+relu output
__device__ float g_pmax[32 * 16 * 64];           // per (b,tile,c) partial max
__device__ int   g_pidx[32 * 16 * 64];           // per (b,tile,c) partial argmax
__device__ float g_psum[32 * 16 * 64];           // per (b,tile,c) partial sum
__device__ float g_part[128 * 32 * 1024];        // dense1 split-K partials
__device__ float g_hidden[32 * 1024];            // dense1 output (post relu)

// ---------------- K1: conv1 (3x3x1->32) + relu + 2x2 maxpool, 4ch/thread ----
__global__ void k_conv1_pool(const float* __restrict__ in,
                             const float* __restrict__ w,
                             const float* __restrict__ bias) {
    int idx = blockIdx.x * 256 + threadIdx.x;     // 32*64*64*8 = 1,048,576
    int cq = idx & 7;                             // channel quad: c = cq*4..+3
    int x = (idx >> 3) & 63;
    int y = (idx >> 9) & 63;
    int b = idx >> 15;

    float2 w0[9], w1[9];
#pragma unroll
    for (int i = 0; i < 9; i++) {
        float4 wv = *(const float4*)(w + i * 32 + cq * 4);
        w0[i].x = wv.x; w0[i].y = wv.y;
        w1[i].x = wv.z; w1[i].y = wv.w;
    }
    float4 bv = *(const float4*)(bias + cq * 4);
    float2 b0; b0.x = bv.x; b0.y = bv.y;
    float2 b1; b1.x = bv.z; b1.y = bv.w;
    const float* ib = in + b * 16384;

    float2 m0 = make_float2(0.f, 0.f), m1 = make_float2(0.f, 0.f);
#pragma unroll
    for (int sy = 0; sy < 2; sy++) {
#pragma unroll
        for (int sx = 0; sx < 2; sx++) {
            int oy = 2 * y + sy, ox = 2 * x + sx;
            float2 a0 = b0, a1 = b1;
#pragma unroll
            for (int ky = 0; ky < 3; ky++) {
                int yy = oy + ky - 1;
                if ((unsigned)yy < 128u) {
#pragma unroll
                    for (int kx = 0; kx < 3; kx++) {
                        int xx = ox + kx - 1;
                        if ((unsigned)xx < 128u) {
                            float iv = ib[yy * 128 + xx];
                            float2 a; a.x = iv; a.y = iv;
                            a0 = ffma2(a, w0[ky * 3 + kx], a0);
                            a1 = ffma2(a, w1[ky * 3 + kx], a1);
                        }
                    }
                }
            }
            m0.x = fmaxf(m0.x, a0.x); m0.y = fmaxf(m0.y, a0.y);
            m1.x = fmaxf(m1.x, a1.x); m1.y = fmaxf(m1.y, a1.y);
        }
    }
    float4 o; o.x = m0.x; o.y = m0.y; o.z = m1.x; o.w = m1.y;
    *(float4*)(g_pool1 + ((b * 4096 + y * 64 + x) * 32 + cq * 4)) = o;
}

// ---------------- K2: conv2 (3x3x32->64, SAME) + relu + fused tile-reduce ----
#define IN_PLANE 360                     // 18 rows x 20 floats; 1440B (16B-mult)
#define CONV2_SMEM (32 * IN_PLANE * 4)   // 46080B
__global__ void __launch_bounds__(256, 2) k_conv2(const float* __restrict__ w,
                                                  const float* __restrict__ bias) {
    extern __shared__ __align__(16) float sm[];
    float* in_s = sm;                    // [32][360]

    int b  = blockIdx.x >> 4;
    int t  = blockIdx.x & 15;
    int ty = t >> 2, tx = t & 3;
    int tid = threadIdx.x;

    for (int i = tid; i < 32 * 18 * 18; i += 256) {
        int ci = i & 31;
        int rest = i >> 5;
        int sy = rest / 18, sx = rest - sy * 18;
        int gy = ty * 16 + sy - 1, gx = tx * 16 + sx - 1;
        float v = 0.f;
        if ((unsigned)gy < 64u && (unsigned)gx < 64u)
            v = g_pool1[((b * 64 + gy) * 64 + gx) * 32 + ci];
        in_s[ci * IN_PLANE + sy * 20 + sx] = v;
    }
    __syncthreads();

    int cg = tid & 7;          // co = cg*8 + [0..8)
    int pg = tid >> 3;         // 0..31 (row-major pixel groups in tile)
    int r  = pg >> 1;          // tile row 0..15
    int x0 = (pg & 1) * 8;     // half-row start (16B-aligned loads)

    float2 acc[8][4];
    {
        const float2* bp = (const float2*)(bias + cg * 8);
#pragma unroll
        for (int jj = 0; jj < 4; jj++) {
            float2 bv = bp[jj];
#pragma unroll
            for (int j = 0; j < 8; j++) acc[j][jj] = bv;
        }
    }

#pragma unroll 1
    for (int ky = 0; ky < 3; ky++) {
        const float* rowb = in_s + (r + ky) * 20 + x0;
        const float4* wb  = (const float4*)(w + (ky * 3) * 2048 + cg * 8);
#pragma unroll 4
        for (int ci = 0; ci < 32; ci++) {
            const float4* ip = (const float4*)(rowb + ci * IN_PLANE);
            float4 fa = ip[0], fb = ip[1], fc = ip[2];
            float f[12] = {fa.x, fa.y, fa.z, fa.w,
                           fb.x, fb.y, fb.z, fb.w,
                           fc.x, fc.y, fc.z, fc.w};
#pragma unroll
            for (int kx = 0; kx < 3; kx++) {
                const float4* wp = wb + (kx * 2048 + ci * 64) / 4;
                float4 wa = __ldg(wp);
                float4 wc = __ldg(wp + 1);
                float2 wv0; wv0.x = wa.x; wv0.y = wa.y;
                float2 wv1; wv1.x = wa.z; wv1.y = wa.w;
                float2 wv2; wv2.x = wc.x; wv2.y = wc.y;
                float2 wv3; wv3.x = wc.z; wv3.y = wc.w;
#pragma unroll
                for (int j = 0; j < 8; j++) {
                    float iv = f[j + kx];
                    float2 a; a.x = iv; a.y = iv;
                    acc[j][0] = ffma2(a, wv0, acc[j][0]);
                    acc[j][1] = ffma2(a, wv1, acc[j][1]);
                    acc[j][2] = ffma2(a, wv2, acc[j][2]);
                    acc[j][3] = ffma2(a, wv3, acc[j][3]);
                }
            }
        }
    }

    int gy  = ty * 16 + r;
    int gxb = tx * 16 + x0;
#pragma unroll
    for (int j = 0; j < 8; j++) {
#pragma unroll
        for (int jj = 0; jj < 4; jj++) {
            acc[j][jj].x = fmaxf(acc[j][jj].x, 0.f);
            acc[j][jj].y = fmaxf(acc[j][jj].y, 0.f);
        }
        *(float2*)(g_conv2 + ((b * 64 + gy) * 64 + gxb + j) * 64 + cg * 8 + 0) = acc[j][0];
        *(float2*)(g_conv2 + ((b * 64 + gy) * 64 + gxb + j) * 64 + cg * 8 + 2) = acc[j][1];
        *(float2*)(g_conv2 + ((b * 64 + gy) * 64 + gxb + j) * 64 + cg * 8 + 4) = acc[j][2];
        *(float2*)(g_conv2 + ((b * 64 + gy) * 64 + gxb + j) * 64 + cg * 8 + 6) = acc[j][3];
    }

    // ---- fused per-tile reduction (max / first-argmax / sum per channel) ----
    __syncthreads();
    float* rmax = in_s;               // [32 pg][64 c]
    float* rsum = in_s + 2048;
    int*   ridx = (int*)(in_s + 4096);

#pragma unroll
    for (int jj = 0; jj < 4; jj++) {
        float m0 = -1.f, m1 = -1.f, s0 = 0.f, s1 = 0.f;
        int i0 = 0, i1 = 0;
#pragma unroll
        for (int j = 0; j < 8; j++) {       // j increasing = pixel order
            float v0 = acc[j][jj].x, v1 = acc[j][jj].y;
            s0 += v0; s1 += v1;
            if (v0 > m0) { m0 = v0; i0 = j; }
            if (v1 > m1) { m1 = v1; i1 = j; }
        }
        int base = gy * 64 + gxb;
        int c0 = cg * 8 + 2 * jj;
        rmax[pg * 64 + c0] = m0;     rmax[pg * 64 + c0 + 1] = m1;
        rsum[pg * 64 + c0] = s0;     rsum[pg * 64 + c0 + 1] = s1;
        ridx[pg * 64 + c0] = base + i0; ridx[pg * 64 + c0 + 1] = base + i1;
    }
    __syncthreads();

    if (tid < 64) {
        int c = tid;
        float B = -1.f, S = 0.f;
        int I = 0x7FFFFFFF;
#pragma unroll
        for (int g = 0; g < 32; g++) {
            float v = rmax[g * 64 + c];
            int   i = ridx[g * 64 + c];
            S += rsum[g * 64 + c];
            if (v > B || (v == B && i < I)) { B = v; I = i; }
        }
        int o = (b * 16 + t) * 64 + c;
        g_pmax[o] = B; g_pidx[o] = I; g_psum[o] = S;
    }
}

// ---------------- K3: mask+relu+pool, amax reduced per-block (2048 CTAs) -----
__global__ void __launch_bounds__(256) k_maskpool(float* __restrict__ outp) {
    int blk = blockIdx.x;            // 2048; 64 blocks per batch
    int tid = threadIdx.x;
    int b   = blk >> 6;

    __shared__ float smu[64][2];     // per-channel (mux, muy)
    if (tid < 64) {
        int c = tid;
        float B = -1.f;
        int I = 0x7FFFFFFF;
#pragma unroll
        for (int t = 0; t < 16; t++) {
            int o = (b * 16 + t) * 64 + c;
            float v = g_pmax[o];
            int   i = g_pidx[o];
            if (v > B || (v == B && i < I)) { B = v; I = i; }
        }
        smu[c][0] = (float)(I >> 6) * (1.f / 31.5f) - 1.f;
        smu[c][1] = (float)(I & 63) * (1.f / 31.5f) - 1.f;
    }
    __syncthreads();

    int idx = blk * 256 + tid;       // quad index over 524288
    int cq = idx & 15;
    int px = (idx >> 4) & 31;
    int py = (idx >> 9) & 31;

    int c0 = cq * 4;
    float mux0 = smu[c0][0],     muy0 = smu[c0][1];
    float mux1 = smu[c0 + 1][0], muy1 = smu[c0 + 1][1];
    float mux2 = smu[c0 + 2][0], muy2 = smu[c0 + 2][1];
    float mux3 = smu[c0 + 3][0], muy3 = smu[c0 + 3][1];

    float4 m = make_float4(0.f, 0.f, 0.f, 0.f);
#pragma unroll
    for (int sy = 0; sy < 2; sy++) {
#pragma unroll
        for (int sx = 0; sx < 2; sx++) {
            int yy = 2 * py + sy, xx = 2 * px + sx;
            float ly = (float)yy * (2.f / 63.f) - 1.f;
            float lx = (float)xx * (2.f / 63.f) - 1.f;
            float4 v = *(const float4*)(g_conv2 + ((b * 64 + yy) * 64 + xx) * 64 + c0);
            float k0 = fmaxf(1.f - 0.5f * (fabsf(ly - mux0) + fabsf(lx - muy0)), -1.f);
            float k1 = fmaxf(1.f - 0.5f * (fabsf(ly - mux1) + fabsf(lx - muy1)), -1.f);
            float k2 = fmaxf(1.f - 0.5f * (fabsf(ly - mux2) + fabsf(lx - muy2)), -1.f);
            float k3 = fmaxf(1.f - 0.5f * (fabsf(ly - mux3) + fabsf(lx - muy3)), -1.f);
            m.x = fmaxf(m.x, v.x * k0);
            m.y = fmaxf(m.y, v.y * k1);
            m.z = fmaxf(m.z, v.z * k2);
            m.w = fmaxf(m.w, v.w * k3);
        }
    }
    ((float4*)outp)[idx] = m;
}

// ---------------- K4: dense1 split-K, cp.async double-buffered w-tiles -------
// M=32, N=1024, K=65536. grid (2 n-halves, 128 k-splits), 256 threads.
// w streamed as 32 sub-tiles of 16k x 512n (32KB) via cp.async.cg into a
// 2-deep smem ring -> 64KB DRAM data in flight per CTA, off the register
// scoreboard. Compute per k: 1 LDS.64 (w) + 8 broadcast LDS.128 (x) + 32 FFMA2.
#define D1_SMEM (128 * 36 * 4 + 2 * 16 * 512 * 4)   // 18432 + 65536 = 83968
__global__ void __launch_bounds__(256, 2) k_dense1(const float* __restrict__ x,
                                                   const float* __restrict__ w) {
    extern __shared__ __align__(16) float dyn[];
    float* xs = dyn;                  // [128][36]
    float* wbuf = dyn + 128 * 36;     // [2][16][512]

    int tid = threadIdx.x;
    int n0 = blockIdx.x * 512 + tid * 2;
    long kbase = (long)blockIdx.y * 512;
    const float* wbase = w + kbase * 1024 + blockIdx.x * 512;

    // per-thread cp.async chunk mapping: 8 chunks of 16B over 16x512 tile
    int c_row[8], c_col[8];
#pragma unroll
    for (int j = 0; j < 8; j++) {
        int c = tid + j * 256;
        c_row[j] = c >> 7;            // 0..15
        c_col[j] = (c & 127) << 2;    // float offset in 512-row
    }

#define D1_PREFETCH(st)                                                        \
    do {                                                                       \
        const float* _src = wbase + (long)(st) * 16 * 1024;                    \
        float* _dst = wbuf + ((st) & 1) * 8192;                                \
        _Pragma("unroll")                                                      \
        for (int _j = 0; _j < 8; _j++) {                                       \
            unsigned _d = (unsigned)__cvta_generic_to_shared(                  \
                _dst + c_row[_j] * 512 + c_col[_j]);                           \
            asm volatile("cp.async.cg.shared.global [%0], [%1], 16;"           \
                         :: "r"(_d), "l"(_src + c_row[_j] * 1024 + c_col[_j])  \
                         : "memory");                                          \
        }                                                                      \
    } while (0)

    float2 a0[16], a1[16];
#pragma unroll
    for (int i = 0; i < 16; i++) {
        a0[i] = make_float2(0.f, 0.f);
        a1[i] = make_float2(0.f, 0.f);
    }

    // prologue: prefetch sub-tiles 0 and 1
    D1_PREFETCH(0);
    asm volatile("cp.async.commit_group;" ::: "memory");
    D1_PREFETCH(1);
    asm volatile("cp.async.commit_group;" ::: "memory");

    for (int t = 0; t < 4; t++) {
        __syncthreads();              // prior compute done; xs free to overwrite
        for (int i = tid; i < 4096; i += 256) {
            int kk = i & 127, bb = i >> 7;
            xs[kk * 36 + bb] = x[bb * 65536 + kbase + t * 128 + kk];
        }
        for (int s = 0; s < 8; s++) {
            int st = t * 8 + s;
            asm volatile("cp.async.wait_group 1;" ::: "memory");
            __syncthreads();          // wbuf[st&1] + xs visible to all

            const float* wrow = wbuf + (st & 1) * 8192 + tid * 2;
            const float* xrow = xs + (s * 16) * 36;
#pragma unroll 4
            for (int kk = 0; kk < 16; kk++) {
                float2 wv = *(const float2*)(wrow + kk * 512);
                float2 w0; w0.x = wv.x; w0.y = wv.x;
                float2 w1; w1.x = wv.y; w1.y = wv.y;
                const float4* xp = (const float4*)(xrow + kk * 36);
#pragma unroll
                for (int q = 0; q < 8; q++) {
                    float4 xv = xp[q];                // batches 4q..4q+3
                    float2 lo; lo.x = xv.x; lo.y = xv.y;
                    float2 hi; hi.x = xv.z; hi.y = xv.w;
                    a0[2 * q]     = ffma2(lo, w0, a0[2 * q]);
                    a0[2 * q + 1] = ffma2(hi, w0, a0[2 * q + 1]);
                    a1[2 * q]     = ffma2(lo, w1, a1[2 * q]);
                    a1[2 * q + 1] = ffma2(hi, w1, a1[2 * q + 1]);
                }
            }
            __syncthreads();          // all warps done reading wbuf[st&1]
            if (st + 2 < 32) D1_PREFETCH(st + 2);
            asm volatile("cp.async.commit_group;" ::: "memory");  // keep count
        }
    }

    float* p = g_part + (size_t)blockIdx.y * 32 * 1024;
#pragma unroll
    for (int bb = 0; bb < 16; bb++) {
        p[(2 * bb) * 1024 + n0]         = a0[bb].x;
        p[(2 * bb + 1) * 1024 + n0]     = a0[bb].y;
        p[(2 * bb) * 1024 + n0 + 1]     = a1[bb].x;
        p[(2 * bb + 1) * 1024 + n0 + 1] = a1[bb].y;
    }
#undef D1_PREFETCH
}

// ---------------- K5: segment-mean -> argmax category per filter -------------
__global__ void k_filters(const int* __restrict__ lab32,
                          float* __restrict__ outf) {
    __shared__ float sc[2048];      // csum[b][c]
    __shared__ float mean[10][64];
    __shared__ int lbl[32];
    int tid = threadIdx.x;

    for (int i = tid; i < 2048; i += 640) {
        int b = i >> 6, c = i & 63;
        float s = 0.f;
#pragma unroll
        for (int t = 0; t < 16; t++) s += g_psum[(b * 16 + t) * 64 + c];
        sc[i] = s;
    }
    if (tid == 0) {
        bool is64 = true;
        for (int i = 1; i < 32; i += 2)
            if (lab32[i] != 0) { is64 = false; break; }
        if (is64) {
            const long long* l64 = (const long long*)lab32;
            for (int b = 0; b < 32; b++) lbl[b] = (int)l64[b];
        } else {
            for (int b = 0; b < 32; b++) lbl[b] = lab32[b];
        }
    }
    __syncthreads();

    {
        int cat = tid / 64, c = tid & 63;
        float s = 0.f; int ct = 0;
        for (int b = 0; b < 32; b++) {
            if (lbl[b] == cat) { s += sc[b * 64 + c]; ct++; }
        }
        mean[cat][c] = s / (float)ct;         // ct==0 -> NaN (numpy: NaN wins)
    }
    __syncthreads();

    if (tid < 64) {
        float best = 0.f;
        int bi = 0;
        bool have = false, bnan = false;
        for (int cat = 0; cat < 10; cat++) {
            float v = mean[cat][tid];
            bool vn = isnan(v);
            if (!bnan && (vn || !have || v > best)) {
                best = v; bi = cat; bnan = vn; have = true;
            }
        }
        outf[tid] = (float)bi;
    }
}

// ---------------- K6: reduce partials + bias + relu --------------------------
__global__ void k_dense1_fin(const float* __restrict__ bias) {
    int idx = blockIdx.x * 256 + threadIdx.x;   // 32*1024
    int n = idx & 1023, b = idx >> 10;
    float s = 0.f;
#pragma unroll 16
    for (int ks = 0; ks < 128; ks++) s += g_part[(ks * 32 + b) * 1024 + n];
    g_hidden[idx] = fmaxf(s + bias[n], 0.f);
}

// ---------------- K7: dense2 -> logits (k-parallel + smem tree) --------------
__global__ void k_dense2(const float* __restrict__ w,
                         const float* __restrict__ bias,
                         float* __restrict__ logits) {
    int b = blockIdx.x;            // 32
    int tid = threadIdx.x;         // 256
    float acc[10];
#pragma unroll
    for (int j = 0; j < 10; j++) acc[j] = 0.f;
    const float* h = g_hidden + b * 1024;
#pragma unroll
    for (int t = 0; t < 4; t++) {
        int k = t * 256 + tid;
        float hv = h[k];
        const float* wr = w + k * 10;
#pragma unroll
        for (int j = 0; j < 10; j++) acc[j] = fmaf(hv, wr[j], acc[j]);
    }
    __shared__ float s[256 * 10];
#pragma unroll
    for (int j = 0; j < 10; j++) s[tid * 10 + j] = acc[j];
    __syncthreads();
    for (int off = 128; off > 0; off >>= 1) {
        if (tid < off) {
#pragma unroll
            for (int j = 0; j < 10; j++)
                s[tid * 10 + j] += s[(tid + off) * 10 + j];
        }
        __syncthreads();
    }
    if (tid < 10) logits[b * 10 + tid] = s[tid] + bias[tid];
}

// ---------------- launcher ---------------------------------------------------
extern "C" void kernel_launch(void* const* d_in, const int* in_sizes, int n_in,
                              void* d_out, int out_size) {
    const float* inputs = (const float*)d_in[0];
    const int*   labels = (const int*)d_in[1];   // dtype resolved on-device
    const float* c1w = (const float*)d_in[2];
    const float* c1b = (const float*)d_in[3];
    const float* c2w = (const float*)d_in[4];
    const float* c2b = (const float*)d_in[5];
    const float* d1w = (const float*)d_in[6];
    const float* d1b = (const float*)d_in[7];
    const float* d2w = (const float*)d_in[8];
    const float* d2b = (const float*)d_in[9];

    float* out = (float*)d_out;
    float* out_logits = out;                       // (32,10)
    float* out_pool   = out + 320;                 // (32,32,32,64)
    float* out_filt   = out + 320 + 2097152;       // (64,)

    static int smem_set = 0;
    if (!smem_set) {
        cudaFuncSetAttribute(k_dense1, cudaFuncAttributeMaxDynamicSharedMemorySize,
                             D1_SMEM);
        smem_set = 1;
    }

    k_conv1_pool<<<4096, 256>>>(inputs, c1w, c1b);
    k_conv2<<<512, 256, CONV2_SMEM>>>(c2w, c2b);
    k_maskpool<<<2048, 256>>>(out_pool);
    k_dense1<<<dim3(2, 128), 256, D1_SMEM>>>(out_pool, d1w);  // slot 3 -> profiled
    k_filters<<<1, 640>>>(labels, out_filt);
    k_dense1_fin<<<128, 256>>>(d1b);
    k_dense2<<<32, 256>>>(d2w, d2b, out_logits);
}

// round 15
// speedup vs baseline: 1.1690x; 1.0060x over previous
#include <cuda_runtime.h>
#include <cstdint>

typedef unsigned long long ull_t;

// packed fp32x2 FMA (sm_100+): two independent fp32 FMAs, bit-exact vs scalar
__device__ __forceinline__ float2 ffma2(float2 a, float2 b, float2 c) {
    float2 d;
    asm("fma.rn.f32x2 %0, %1, %2, %3;"
        : "=l"(reinterpret_cast<ull_t&>(d))
        : "l"(reinterpret_cast<ull_t&>(a)),
          "l"(reinterpret_cast<ull_t&>(b)),
          "l"(reinterpret_cast<ull_t&>(c)));
    return d;
}

// ---------------- scratch (device globals; no allocations allowed) ----------
__device__ float g_pool1[32 * 64 * 64 * 32];     // conv1+pool output
__device__ float g_conv2[32 * 64 * 64 * 64];     // conv2+relu output
__device__ float g_pmax[32 * 16 * 64];           // per (b,tile,c) partial max
__device__ int   g_pidx[32 * 16 * 64];           // per (b,tile,c) partial argmax
__device__ float g_psum[32 * 16 * 64];           // per (b,tile,c) partial sum
__device__ float g_part[128 * 32 * 1024];        // dense1 split-K partials
__device__ float g_hidden[32 * 1024];            // dense1 output (post relu)

// ---------------- K1: conv1 (3x3x1->32) + relu + 2x2 maxpool, 4ch/thread ----
__global__ void k_conv1_pool(const float* __restrict__ in,
                             const float* __restrict__ w,
                             const float* __restrict__ bias) {
    int idx = blockIdx.x * 256 + threadIdx.x;     // 32*64*64*8 = 1,048,576
    int cq = idx & 7;                             // channel quad: c = cq*4..+3
    int x = (idx >> 3) & 63;
    int y = (idx >> 9) & 63;
    int b = idx >> 15;

    float2 w0[9], w1[9];
#pragma unroll
    for (int i = 0; i < 9; i++) {
        float4 wv = *(const float4*)(w + i * 32 + cq * 4);
        w0[i].x = wv.x; w0[i].y = wv.y;
        w1[i].x = wv.z; w1[i].y = wv.w;
    }
    float4 bv = *(const float4*)(bias + cq * 4);
    float2 b0; b0.x = bv.x; b0.y = bv.y;
    float2 b1; b1.x = bv.z; b1.y = bv.w;
    const float* ib = in + b * 16384;

    float2 m0 = make_float2(0.f, 0.f), m1 = make_float2(0.f, 0.f);
#pragma unroll
    for (int sy = 0; sy < 2; sy++) {
#pragma unroll
        for (int sx = 0; sx < 2; sx++) {
            int oy = 2 * y + sy, ox = 2 * x + sx;
            float2 a0 = b0, a1 = b1;
#pragma unroll
            for (int ky = 0; ky < 3; ky++) {
                int yy = oy + ky - 1;
                if ((unsigned)yy < 128u) {
#pragma unroll
                    for (int kx = 0; kx < 3; kx++) {
                        int xx = ox + kx - 1;
                        if ((unsigned)xx < 128u) {
                            float iv = ib[yy * 128 + xx];
                            float2 a; a.x = iv; a.y = iv;
                            a0 = ffma2(a, w0[ky * 3 + kx], a0);
                            a1 = ffma2(a, w1[ky * 3 + kx], a1);
                        }
                    }
                }
            }
            m0.x = fmaxf(m0.x, a0.x); m0.y = fmaxf(m0.y, a0.y);
            m1.x = fmaxf(m1.x, a1.x); m1.y = fmaxf(m1.y, a1.y);
        }
    }
    float4 o; o.x = m0.x; o.y = m0.y; o.z = m1.x; o.w = m1.y;
    *(float4*)(g_pool1 + ((b * 4096 + y * 64 + x) * 32 + cq * 4)) = o;
}

// ---------------- K2: conv2 (3x3x32->64, SAME) + relu + fused tile-reduce ----
#define IN_PLANE 360                     // 18 rows x 20 floats; 1440B (16B-mult)
#define CONV2_SMEM (32 * IN_PLANE * 4)   // 46080B
__global__ void __launch_bounds__(256, 2) k_conv2(const float* __restrict__ w,
                                                  const float* __restrict__ bias) {
    extern __shared__ __align__(16) float sm[];
    float* in_s = sm;                    // [32][360]

    int b  = blockIdx.x >> 4;
    int t  = blockIdx.x & 15;
    int ty = t >> 2, tx = t & 3;
    int tid = threadIdx.x;

    for (int i = tid; i < 32 * 18 * 18; i += 256) {
        int ci = i & 31;
        int rest = i >> 5;
        int sy = rest / 18, sx = rest - sy * 18;
        int gy = ty * 16 + sy - 1, gx = tx * 16 + sx - 1;
        float v = 0.f;
        if ((unsigned)gy < 64u && (unsigned)gx < 64u)
            v = g_pool1[((b * 64 + gy) * 64 + gx) * 32 + ci];
        in_s[ci * IN_PLANE + sy * 20 + sx] = v;
    }
    __syncthreads();

    int cg = tid & 7;          // co = cg*8 + [0..8)
    int pg = tid >> 3;         // 0..31 (row-major pixel groups in tile)
    int r  = pg >> 1;          // tile row 0..15
    int x0 = (pg & 1) * 8;     // half-row start (16B-aligned loads)

    float2 acc[8][4];
    {
        const float2* bp = (const float2*)(bias + cg * 8);
#pragma unroll
        for (int jj = 0; jj < 4; jj++) {
            float2 bv = bp[jj];
#pragma unroll
            for (int j = 0; j < 8; j++) acc[j][jj] = bv;
        }
    }

#pragma unroll 1
    for (int ky = 0; ky < 3; ky++) {
        const float* rowb = in_s + (r + ky) * 20 + x0;
        const float4* wb  = (const float4*)(w + (ky * 3) * 2048 + cg * 8);
#pragma unroll 4
        for (int ci = 0; ci < 32; ci++) {
            const float4* ip = (const float4*)(rowb + ci * IN_PLANE);
            float4 fa = ip[0], fb = ip[1], fc = ip[2];
            float f[12] = {fa.x, fa.y, fa.z, fa.w,
                           fb.x, fb.y, fb.z, fb.w,
                           fc.x, fc.y, fc.z, fc.w};
#pragma unroll
            for (int kx = 0; kx < 3; kx++) {
                const float4* wp = wb + (kx * 2048 + ci * 64) / 4;
                float4 wa = __ldg(wp);
                float4 wc = __ldg(wp + 1);
                float2 wv0; wv0.x = wa.x; wv0.y = wa.y;
                float2 wv1; wv1.x = wa.z; wv1.y = wa.w;
                float2 wv2; wv2.x = wc.x; wv2.y = wc.y;
                float2 wv3; wv3.x = wc.z; wv3.y = wc.w;
#pragma unroll
                for (int j = 0; j < 8; j++) {
                    float iv = f[j + kx];
                    float2 a; a.x = iv; a.y = iv;
                    acc[j][0] = ffma2(a, wv0, acc[j][0]);
                    acc[j][1] = ffma2(a, wv1, acc[j][1]);
                    acc[j][2] = ffma2(a, wv2, acc[j][2]);
                    acc[j][3] = ffma2(a, wv3, acc[j][3]);
                }
            }
        }
    }

    int gy  = ty * 16 + r;
    int gxb = tx * 16 + x0;
#pragma unroll
    for (int j = 0; j < 8; j++) {
#pragma unroll
        for (int jj = 0; jj < 4; jj++) {
            acc[j][jj].x = fmaxf(acc[j][jj].x, 0.f);
            acc[j][jj].y = fmaxf(acc[j][jj].y, 0.f);
        }
        *(float2*)(g_conv2 + ((b * 64 + gy) * 64 + gxb + j) * 64 + cg * 8 + 0) = acc[j][0];
        *(float2*)(g_conv2 + ((b * 64 + gy) * 64 + gxb + j) * 64 + cg * 8 + 2) = acc[j][1];
        *(float2*)(g_conv2 + ((b * 64 + gy) * 64 + gxb + j) * 64 + cg * 8 + 4) = acc[j][2];
        *(float2*)(g_conv2 + ((b * 64 + gy) * 64 + gxb + j) * 64 + cg * 8 + 6) = acc[j][3];
    }

    // ---- fused per-tile reduction (max / first-argmax / sum per channel) ----
    __syncthreads();
    float* rmax = in_s;               // [32 pg][64 c]
    float* rsum = in_s + 2048;
    int*   ridx = (int*)(in_s + 4096);

#pragma unroll
    for (int jj = 0; jj < 4; jj++) {
        float m0 = -1.f, m1 = -1.f, s0 = 0.f, s1 = 0.f;
        int i0 = 0, i1 = 0;
#pragma unroll
        for (int j = 0; j < 8; j++) {       // j increasing = pixel order
            float v0 = acc[j][jj].x, v1 = acc[j][jj].y;
            s0 += v0; s1 += v1;
            if (v0 > m0) { m0 = v0; i0 = j; }
            if (v1 > m1) { m1 = v1; i1 = j; }
        }
        int base = gy * 64 + gxb;
        int c0 = cg * 8 + 2 * jj;
        rmax[pg * 64 + c0] = m0;     rmax[pg * 64 + c0 + 1] = m1;
        rsum[pg * 64 + c0] = s0;     rsum[pg * 64 + c0 + 1] = s1;
        ridx[pg * 64 + c0] = base + i0; ridx[pg * 64 + c0 + 1] = base + i1;
    }
    __syncthreads();

    if (tid < 64) {
        int c = tid;
        float B = -1.f, S = 0.f;
        int I = 0x7FFFFFFF;
#pragma unroll
        for (int g = 0; g < 32; g++) {
            float v = rmax[g * 64 + c];
            int   i = ridx[g * 64 + c];
            S += rsum[g * 64 + c];
            if (v > B || (v == B && i < I)) { B = v; I = i; }
        }
        int o = (b * 16 + t) * 64 + c;
        g_pmax[o] = B; g_pidx[o] = I; g_psum[o] = S;
    }
}

// ---------------- K3: mask+relu+pool, amax reduced per-block (2048 CTAs) -----
__global__ void __launch_bounds__(256) k_maskpool(float* __restrict__ outp) {
    int blk = blockIdx.x;            // 2048; 64 blocks per batch
    int tid = threadIdx.x;
    int b   = blk >> 6;

    __shared__ float smu[64][2];     // per-channel (mux, muy)
    if (tid < 64) {
        int c = tid;
        float B = -1.f;
        int I = 0x7FFFFFFF;
#pragma unroll
        for (int t = 0; t < 16; t++) {
            int o = (b * 16 + t) * 64 + c;
            float v = g_pmax[o];
            int   i = g_pidx[o];
            if (v > B || (v == B && i < I)) { B = v; I = i; }
        }
        smu[c][0] = (float)(I >> 6) * (1.f / 31.5f) - 1.f;
        smu[c][1] = (float)(I & 63) * (1.f / 31.5f) - 1.f;
    }
    __syncthreads();

    int idx = blk * 256 + tid;       // quad index over 524288
    int cq = idx & 15;
    int px = (idx >> 4) & 31;
    int py = (idx >> 9) & 31;

    int c0 = cq * 4;
    float mux0 = smu[c0][0],     muy0 = smu[c0][1];
    float mux1 = smu[c0 + 1][0], muy1 = smu[c0 + 1][1];
    float mux2 = smu[c0 + 2][0], muy2 = smu[c0 + 2][1];
    float mux3 = smu[c0 + 3][0], muy3 = smu[c0 + 3][1];

    float4 m = make_float4(0.f, 0.f, 0.f, 0.f);
#pragma unroll
    for (int sy = 0; sy < 2; sy++) {
#pragma unroll
        for (int sx = 0; sx < 2; sx++) {
            int yy = 2 * py + sy, xx = 2 * px + sx;
            float ly = (float)yy * (2.f / 63.f) - 1.f;
            float lx = (float)xx * (2.f / 63.f) - 1.f;
            float4 v = *(const float4*)(g_conv2 + ((b * 64 + yy) * 64 + xx) * 64 + c0);
            float k0 = fmaxf(1.f - 0.5f * (fabsf(ly - mux0) + fabsf(lx - muy0)), -1.f);
            float k1 = fmaxf(1.f - 0.5f * (fabsf(ly - mux1) + fabsf(lx - muy1)), -1.f);
            float k2 = fmaxf(1.f - 0.5f * (fabsf(ly - mux2) + fabsf(lx - muy2)), -1.f);
            float k3 = fmaxf(1.f - 0.5f * (fabsf(ly - mux3) + fabsf(lx - muy3)), -1.f);
            m.x = fmaxf(m.x, v.x * k0);
            m.y = fmaxf(m.y, v.y * k1);
            m.z = fmaxf(m.z, v.z * k2);
            m.w = fmaxf(m.w, v.w * k3);
        }
    }
    ((float4*)outp)[idx] = m;
}

// ---------------- K4: dense1 split-K, cp.async ring + 4n x 16b compute -------
// M=32, N=1024, K=65536. grid (2 n-halves, 128 k-splits), 256 threads.
// w streamed as 32 sub-tiles of 16k x 512n (32KB) via cp.async.cg (2-deep ring).
// Thread (nq=tid&127, bh=tid>>7): n = nq*4..+3 (1 conflict-free LDS.128),
// batches bh*16..+15 (4 broadcast LDS.128). Per k: 5 LDS + 32 FFMA2.
#define D1_SMEM (128 * 36 * 4 + 2 * 16 * 512 * 4)   // 18432 + 65536 = 83968
__global__ void __launch_bounds__(256, 2) k_dense1(const float* __restrict__ x,
                                                   const float* __restrict__ w) {
    extern __shared__ __align__(16) float dyn[];
    float* xs = dyn;                  // [128][36]
    float* wbuf = dyn + 128 * 36;     // [2][16][512]

    int tid = threadIdx.x;
    int nq  = tid & 127;
    int bh  = tid >> 7;
    int n0 = blockIdx.x * 512 + nq * 4;
    long kbase = (long)blockIdx.y * 512;
    const float* wbase = w + kbase * 1024 + blockIdx.x * 512;

    // per-thread cp.async chunk mapping: 8 chunks of 16B over 16x512 tile
    int c_row[8], c_col[8];
#pragma unroll
    for (int j = 0; j < 8; j++) {
        int c = tid + j * 256;
        c_row[j] = c >> 7;            // 0..15
        c_col[j] = (c & 127) << 2;    // float offset in 512-row
    }

#define D1_PREFETCH(st)                                                        \
    do {                                                                       \
        const float* _src = wbase + (long)(st) * 16 * 1024;                    \
        float* _dst = wbuf + ((st) & 1) * 8192;                                \
        _Pragma("unroll")                                                      \
        for (int _j = 0; _j < 8; _j++) {                                       \
            unsigned _d = (unsigned)__cvta_generic_to_shared(                  \
                _dst + c_row[_j] * 512 + c_col[_j]);                           \
            asm volatile("cp.async.cg.shared.global [%0], [%1], 16;"           \
                         :: "r"(_d), "l"(_src + c_row[_j] * 1024 + c_col[_j])  \
                         : "memory");                                          \
        }                                                                      \
    } while (0)

    float2 acc[4][8];                 // [n][bpair] batches bh*16 + 2p,2p+1
#pragma unroll
    for (int n = 0; n < 4; n++)
#pragma unroll
        for (int p = 0; p < 8; p++) acc[n][p] = make_float2(0.f, 0.f);

    // prologue: prefetch sub-tiles 0 and 1
    D1_PREFETCH(0);
    asm volatile("cp.async.commit_group;" ::: "memory");
    D1_PREFETCH(1);
    asm volatile("cp.async.commit_group;" ::: "memory");

    for (int t = 0; t < 4; t++) {
        __syncthreads();              // prior compute done; xs free to overwrite
        for (int i = tid; i < 4096; i += 256) {
            int kk = i & 127, bb = i >> 7;
            xs[kk * 36 + bb] = x[bb * 65536 + kbase + t * 128 + kk];
        }
        for (int s = 0; s < 8; s++) {
            int st = t * 8 + s;
            asm volatile("cp.async.wait_group 1;" ::: "memory");
            __syncthreads();          // wbuf[st&1] + xs visible to all

            const float* wrow = wbuf + (st & 1) * 8192 + nq * 4;
            const float* xrow = xs + (s * 16) * 36 + bh * 16;
#pragma unroll 4
            for (int kk = 0; kk < 16; kk++) {
                float4 wv = *(const float4*)(wrow + kk * 512);
                float2 wn0; wn0.x = wv.x; wn0.y = wv.x;
                float2 wn1; wn1.x = wv.y; wn1.y = wv.y;
                float2 wn2; wn2.x = wv.z; wn2.y = wv.z;
                float2 wn3; wn3.x = wv.w; wn3.y = wv.w;
                const float4* xp = (const float4*)(xrow + kk * 36);
#pragma unroll
                for (int q = 0; q < 4; q++) {
                    float4 xv = xp[q];                // batches bh*16+4q..+3
                    float2 lo; lo.x = xv.x; lo.y = xv.y;
                    float2 hi; hi.x = xv.z; hi.y = xv.w;
                    acc[0][2 * q]     = ffma2(lo, wn0, acc[0][2 * q]);
                    acc[0][2 * q + 1] = ffma2(hi, wn0, acc[0][2 * q + 1]);
                    acc[1][2 * q]     = ffma2(lo, wn1, acc[1][2 * q]);
                    acc[1][2 * q + 1] = ffma2(hi, wn1, acc[1][2 * q + 1]);
                    acc[2][2 * q]     = ffma2(lo, wn2, acc[2][2 * q]);
                    acc[2][2 * q + 1] = ffma2(hi, wn2, acc[2][2 * q + 1]);
                    acc[3][2 * q]     = ffma2(lo, wn3, acc[3][2 * q]);
                    acc[3][2 * q + 1] = ffma2(hi, wn3, acc[3][2 * q + 1]);
                }
            }
            __syncthreads();          // all warps done reading wbuf[st&1]
            if (st + 2 < 32) D1_PREFETCH(st + 2);
            asm volatile("cp.async.commit_group;" ::: "memory");  // keep count
        }
    }

    float* p = g_part + (size_t)blockIdx.y * 32 * 1024;
#pragma unroll
    for (int q = 0; q < 8; q++) {
        int b0 = bh * 16 + 2 * q;
#pragma unroll
        for (int n = 0; n < 4; n++) {
            p[b0 * 1024 + n0 + n]       = acc[n][q].x;
            p[(b0 + 1) * 1024 + n0 + n] = acc[n][q].y;
        }
    }
#undef D1_PREFETCH
}

// ---------------- K5: segment-mean -> argmax category per filter -------------
__global__ void k_filters(const int* __restrict__ lab32,
                          float* __restrict__ outf) {
    __shared__ float sc[2048];      // csum[b][c]
    __shared__ float mean[10][64];
    __shared__ int lbl[32];
    int tid = threadIdx.x;

    for (int i = tid; i < 2048; i += 640) {
        int b = i >> 6, c = i & 63;
        float s = 0.f;
#pragma unroll
        for (int t = 0; t < 16; t++) s += g_psum[(b * 16 + t) * 64 + c];
        sc[i] = s;
    }
    if (tid == 0) {
        bool is64 = true;
        for (int i = 1; i < 32; i += 2)
            if (lab32[i] != 0) { is64 = false; break; }
        if (is64) {
            const long long* l64 = (const long long*)lab32;
            for (int b = 0; b < 32; b++) lbl[b] = (int)l64[b];
        } else {
            for (int b = 0; b < 32; b++) lbl[b] = lab32[b];
        }
    }
    __syncthreads();

    {
        int cat = tid / 64, c = tid & 63;
        float s = 0.f; int ct = 0;
        for (int b = 0; b < 32; b++) {
            if (lbl[b] == cat) { s += sc[b * 64 + c]; ct++; }
        }
        mean[cat][c] = s / (float)ct;         // ct==0 -> NaN (numpy: NaN wins)
    }
    __syncthreads();

    if (tid < 64) {
        float best = 0.f;
        int bi = 0;
        bool have = false, bnan = false;
        for (int cat = 0; cat < 10; cat++) {
            float v = mean[cat][tid];
            bool vn = isnan(v);
            if (!bnan && (vn || !have || v > best)) {
                best = v; bi = cat; bnan = vn; have = true;
            }
        }
        outf[tid] = (float)bi;
    }
}

// ---------------- K6: reduce partials + bias + relu --------------------------
__global__ void k_dense1_fin(const float* __restrict__ bias) {
    int idx = blockIdx.x * 256 + threadIdx.x;   // 32*1024
    int n = idx & 1023, b = idx >> 10;
    float s = 0.f;
#pragma unroll 16
    for (int ks = 0; ks < 128; ks++) s += g_part[(ks * 32 + b) * 1024 + n];
    g_hidden[idx] = fmaxf(s + bias[n], 0.f);
}

// ---------------- K7: dense2 -> logits (k-parallel + smem tree) --------------
__global__ void k_dense2(const float* __restrict__ w,
                         const float* __restrict__ bias,
                         float* __restrict__ logits) {
    int b = blockIdx.x;            // 32
    int tid = threadIdx.x;         // 256
    float acc[10];
#pragma unroll
    for (int j = 0; j < 10; j++) acc[j] = 0.f;
    const float* h = g_hidden + b * 1024;
#pragma unroll
    for (int t = 0; t < 4; t++) {
        int k = t * 256 + tid;
        float hv = h[k];
        const float* wr = w + k * 10;
#pragma unroll
        for (int j = 0; j < 10; j++) acc[j] = fmaf(hv, wr[j], acc[j]);
    }
    __shared__ float s[256 * 10];
#pragma unroll
    for (int j = 0; j < 10; j++) s[tid * 10 + j] = acc[j];
    __syncthreads();
    for (int off = 128; off > 0; off >>= 1) {
        if (tid < off) {
#pragma unroll
            for (int j = 0; j < 10; j++)
                s[tid * 10 + j] += s[(tid + off) * 10 + j];
        }
        __syncthreads();
    }
    if (tid < 10) logits[b * 10 + tid] = s[tid] + bias[tid];
}

// ---------------- launcher ---------------------------------------------------
extern "C" void kernel_launch(void* const* d_in, const int* in_sizes, int n_in,
                              void* d_out, int out_size) {
    const float* inputs = (const float*)d_in[0];
    const int*   labels = (const int*)d_in[1];   // dtype resolved on-device
    const float* c1w = (const float*)d_in[2];
    const float* c1b = (const float*)d_in[3];
    const float* c2w = (const float*)d_in[4];
    const float* c2b = (const float*)d_in[5];
    const float* d1w = (const float*)d_in[6];
    const float* d1b = (const float*)d_in[7];
    const float* d2w = (const float*)d_in[8];
    const float* d2b = (const float*)d_in[9];

    float* out = (float*)d_out;
    float* out_logits = out;                       // (32,10)
    float* out_pool   = out + 320;                 // (32,32,32,64)
    float* out_filt   = out + 320 + 2097152;       // (64,)

    static int smem_set = 0;
    if (!smem_set) {
        cudaFuncSetAttribute(k_dense1, cudaFuncAttributeMaxDynamicSharedMemorySize,
                             D1_SMEM);
        smem_set = 1;
    }

    k_conv1_pool<<<4096, 256>>>(inputs, c1w, c1b);
    k_conv2<<<512, 256, CONV2_SMEM>>>(c2w, c2b);
    k_maskpool<<<2048, 256>>>(out_pool);
    k_dense1<<<dim3(2, 128), 256, D1_SMEM>>>(out_pool, d1w);  // slot 3 -> profiled
    k_filters<<<1, 640>>>(labels, out_filt);
    k_dense1_fin<<<128, 256>>>(d1b);
    k_dense2<<<32, 256>>>(d2w, d2b, out_logits);
}

// round 16
// speedup vs baseline: 1.2159x; 1.0401x over previous
#include <cuda_runtime.h>
#include <cstdint>

typedef unsigned long long ull_t;

// packed fp32x2 FMA (sm_100+): two independent fp32 FMAs, bit-exact vs scalar
__device__ __forceinline__ float2 ffma2(float2 a, float2 b, float2 c) {
    float2 d;
    asm("fma.rn.f32x2 %0, %1, %2, %3;"
        : "=l"(reinterpret_cast<ull_t&>(d))
        : "l"(reinterpret_cast<ull_t&>(a)),
          "l"(reinterpret_cast<ull_t&>(b)),
          "l"(reinterpret_cast<ull_t&>(c)));
    return d;
}

// ---------------- scratch (device globals; no allocations allowed) ----------
__device__ float g_pool1[32 * 64 * 64 * 32];     // conv1+pool output
__device__ float g_conv2[32 * 64 * 64 * 64];     // conv2+relu output
__device__ float g_pmax[32 * 16 * 64];           // per (b,tile,c) partial max
__device__ int   g_pidx[32 * 16 * 64];           // per (b,tile,c) partial argmax
__device__ float g_psum[32 * 16 * 64];           // per (b,tile,c) partial sum
__device__ float g_part[128 * 32 * 1024];        // dense1 split-K partials
__device__ float g_hidden[32 * 1024];            // dense1 output (post relu)

// ---------------- dummy (launch-slot alignment for ncu capture) --------------
__global__ void k_nop(void) {}

// ---------------- K1: conv1 (3x3x1->32) + relu + 2x2 maxpool, 4ch/thread ----
__global__ void k_conv1_pool(const float* __restrict__ in,
                             const float* __restrict__ w,
                             const float* __restrict__ bias) {
    int idx = blockIdx.x * 256 + threadIdx.x;     // 32*64*64*8 = 1,048,576
    int cq = idx & 7;                             // channel quad: c = cq*4..+3
    int x = (idx >> 3) & 63;
    int y = (idx >> 9) & 63;
    int b = idx >> 15;

    float2 w0[9], w1[9];
#pragma unroll
    for (int i = 0; i < 9; i++) {
        float4 wv = *(const float4*)(w + i * 32 + cq * 4);
        w0[i].x = wv.x; w0[i].y = wv.y;
        w1[i].x = wv.z; w1[i].y = wv.w;
    }
    float4 bv = *(const float4*)(bias + cq * 4);
    float2 b0; b0.x = bv.x; b0.y = bv.y;
    float2 b1; b1.x = bv.z; b1.y = bv.w;
    const float* ib = in + b * 16384;

    float2 m0 = make_float2(0.f, 0.f), m1 = make_float2(0.f, 0.f);
#pragma unroll
    for (int sy = 0; sy < 2; sy++) {
#pragma unroll
        for (int sx = 0; sx < 2; sx++) {
            int oy = 2 * y + sy, ox = 2 * x + sx;
            float2 a0 = b0, a1 = b1;
#pragma unroll
            for (int ky = 0; ky < 3; ky++) {
                int yy = oy + ky - 1;
                if ((unsigned)yy < 128u) {
#pragma unroll
                    for (int kx = 0; kx < 3; kx++) {
                        int xx = ox + kx - 1;
                        if ((unsigned)xx < 128u) {
                            float iv = ib[yy * 128 + xx];
                            float2 a; a.x = iv; a.y = iv;
                            a0 = ffma2(a, w0[ky * 3 + kx], a0);
                            a1 = ffma2(a, w1[ky * 3 + kx], a1);
                        }
                    }
                }
            }
            m0.x = fmaxf(m0.x, a0.x); m0.y = fmaxf(m0.y, a0.y);
            m1.x = fmaxf(m1.x, a1.x); m1.y = fmaxf(m1.y, a1.y);
        }
    }
    float4 o; o.x = m0.x; o.y = m0.y; o.z = m1.x; o.w = m1.y;
    *(float4*)(g_pool1 + ((b * 4096 + y * 64 + x) * 32 + cq * 4)) = o;
}

// ---------------- K2: conv2 (3x3x32->64, SAME) + relu + fused tile-reduce ----
// Weights staged per-ky into smem (24KB slice, contiguous in w) -> all weight
// reads are LDS; removes the L1tex wavefront bottleneck of per-warp LDG.128.
#define IN_PLANE 360                     // 18 rows x 20 floats; 1440B (16B-mult)
#define CONV2_SMEM ((32 * IN_PLANE + 3 * 32 * 64) * 4)   // 46080+24576 = 70656B
__global__ void __launch_bounds__(256, 2) k_conv2(const float* __restrict__ w,
                                                  const float* __restrict__ bias) {
    extern __shared__ __align__(16) float sm[];
    float* in_s = sm;                    // [32][360]
    float* w_s  = sm + 32 * IN_PLANE;    // [3 kx][32 ci][64 co] (one ky slice)

    int b  = blockIdx.x >> 4;
    int t  = blockIdx.x & 15;
    int ty = t >> 2, tx = t & 3;
    int tid = threadIdx.x;

    for (int i = tid; i < 32 * 18 * 18; i += 256) {
        int ci = i & 31;
        int rest = i >> 5;
        int sy = rest / 18, sx = rest - sy * 18;
        int gy = ty * 16 + sy - 1, gx = tx * 16 + sx - 1;
        float v = 0.f;
        if ((unsigned)gy < 64u && (unsigned)gx < 64u)
            v = g_pool1[((b * 64 + gy) * 64 + gx) * 32 + ci];
        in_s[ci * IN_PLANE + sy * 20 + sx] = v;
    }

    int cg = tid & 7;          // co = cg*8 + [0..8)
    int pg = tid >> 3;         // 0..31 (row-major pixel groups in tile)
    int r  = pg >> 1;          // tile row 0..15
    int x0 = (pg & 1) * 8;     // half-row start (16B-aligned loads)

    float2 acc[8][4];
    {
        const float2* bp = (const float2*)(bias + cg * 8);
#pragma unroll
        for (int jj = 0; jj < 4; jj++) {
            float2 bv = bp[jj];
#pragma unroll
            for (int j = 0; j < 8; j++) acc[j][jj] = bv;
        }
    }

#pragma unroll 1
    for (int ky = 0; ky < 3; ky++) {
        __syncthreads();               // in_s ready (ky=0) / prior ky reads done
        // stage this ky's weight slice: 6144 contiguous floats
        for (int i = tid; i < 6144; i += 256)
            w_s[i] = w[ky * 6144 + i];
        __syncthreads();

        const float* rowb = in_s + (r + ky) * 20 + x0;
#pragma unroll 4
        for (int ci = 0; ci < 32; ci++) {
            const float4* ip = (const float4*)(rowb + ci * IN_PLANE);
            float4 fa = ip[0], fb = ip[1], fc = ip[2];
            float f[12] = {fa.x, fa.y, fa.z, fa.w,
                           fb.x, fb.y, fb.z, fb.w,
                           fc.x, fc.y, fc.z, fc.w};
#pragma unroll
            for (int kx = 0; kx < 3; kx++) {
                const float4* wp = (const float4*)(w_s + kx * 2048 + ci * 64 + cg * 8);
                float4 wa = wp[0];
                float4 wc = wp[1];
                float2 wv0; wv0.x = wa.x; wv0.y = wa.y;
                float2 wv1; wv1.x = wa.z; wv1.y = wa.w;
                float2 wv2; wv2.x = wc.x; wv2.y = wc.y;
                float2 wv3; wv3.x = wc.z; wv3.y = wc.w;
#pragma unroll
                for (int j = 0; j < 8; j++) {
                    float iv = f[j + kx];
                    float2 a; a.x = iv; a.y = iv;
                    acc[j][0] = ffma2(a, wv0, acc[j][0]);
                    acc[j][1] = ffma2(a, wv1, acc[j][1]);
                    acc[j][2] = ffma2(a, wv2, acc[j][2]);
                    acc[j][3] = ffma2(a, wv3, acc[j][3]);
                }
            }
        }
    }

    int gy  = ty * 16 + r;
    int gxb = tx * 16 + x0;
#pragma unroll
    for (int j = 0; j < 8; j++) {
#pragma unroll
        for (int jj = 0; jj < 4; jj++) {
            acc[j][jj].x = fmaxf(acc[j][jj].x, 0.f);
            acc[j][jj].y = fmaxf(acc[j][jj].y, 0.f);
        }
        *(float2*)(g_conv2 + ((b * 64 + gy) * 64 + gxb + j) * 64 + cg * 8 + 0) = acc[j][0];
        *(float2*)(g_conv2 + ((b * 64 + gy) * 64 + gxb + j) * 64 + cg * 8 + 2) = acc[j][1];
        *(float2*)(g_conv2 + ((b * 64 + gy) * 64 + gxb + j) * 64 + cg * 8 + 4) = acc[j][2];
        *(float2*)(g_conv2 + ((b * 64 + gy) * 64 + gxb + j) * 64 + cg * 8 + 6) = acc[j][3];
    }

    // ---- fused per-tile reduction (max / first-argmax / sum per channel) ----
    __syncthreads();                  // done with in_s; reuse it
    float* rmax = in_s;               // [32 pg][64 c]
    float* rsum = in_s + 2048;
    int*   ridx = (int*)(in_s + 4096);

#pragma unroll
    for (int jj = 0; jj < 4; jj++) {
        float m0 = -1.f, m1 = -1.f, s0 = 0.f, s1 = 0.f;
        int i0 = 0, i1 = 0;
#pragma unroll
        for (int j = 0; j < 8; j++) {       // j increasing = pixel order
            float v0 = acc[j][jj].x, v1 = acc[j][jj].y;
            s0 += v0; s1 += v1;
            if (v0 > m0) { m0 = v0; i0 = j; }
            if (v1 > m1) { m1 = v1; i1 = j; }
        }
        int base = gy * 64 + gxb;
        int c0 = cg * 8 + 2 * jj;
        rmax[pg * 64 + c0] = m0;     rmax[pg * 64 + c0 + 1] = m1;
        rsum[pg * 64 + c0] = s0;     rsum[pg * 64 + c0 + 1] = s1;
        ridx[pg * 64 + c0] = base + i0; ridx[pg * 64 + c0 + 1] = base + i1;
    }
    __syncthreads();

    if (tid < 64) {
        int c = tid;
        float B = -1.f, S = 0.f;
        int I = 0x7FFFFFFF;
#pragma unroll
        for (int g = 0; g < 32; g++) {
            float v = rmax[g * 64 + c];
            int   i = ridx[g * 64 + c];
            S += rsum[g * 64 + c];
            if (v > B || (v == B && i < I)) { B = v; I = i; }
        }
        int o = (b * 16 + t) * 64 + c;
        g_pmax[o] = B; g_pidx[o] = I; g_psum[o] = S;
    }
}

// ---------------- K3: mask+relu+pool, amax reduced per-block (2048 CTAs) -----
__global__ void __launch_bounds__(256) k_maskpool(float* __restrict__ outp) {
    int blk = blockIdx.x;            // 2048; 64 blocks per batch
    int tid = threadIdx.x;
    int b   = blk >> 6;

    __shared__ float smu[64][2];     // per-channel (mux, muy)
    if (tid < 64) {
        int c = tid;
        float B = -1.f;
        int I = 0x7FFFFFFF;
#pragma unroll
        for (int t = 0; t < 16; t++) {
            int o = (b * 16 + t) * 64 + c;
            float v = g_pmax[o];
            int   i = g_pidx[o];
            if (v > B || (v == B && i < I)) { B = v; I = i; }
        }
        smu[c][0] = (float)(I >> 6) * (1.f / 31.5f) - 1.f;
        smu[c][1] = (float)(I & 63) * (1.f / 31.5f) - 1.f;
    }
    __syncthreads();

    int idx = blk * 256 + tid;       // quad index over 524288
    int cq = idx & 15;
    int px = (idx >> 4) & 31;
    int py = (idx >> 9) & 31;

    int c0 = cq * 4;
    float mux0 = smu[c0][0],     muy0 = smu[c0][1];
    float mux1 = smu[c0 + 1][0], muy1 = smu[c0 + 1][1];
    float mux2 = smu[c0 + 2][0], muy2 = smu[c0 + 2][1];
    float mux3 = smu[c0 + 3][0], muy3 = smu[c0 + 3][1];

    float4 m = make_float4(0.f, 0.f, 0.f, 0.f);
#pragma unroll
    for (int sy = 0; sy < 2; sy++) {
#pragma unroll
        for (int sx = 0; sx < 2; sx++) {
            int yy = 2 * py + sy, xx = 2 * px + sx;
            float ly = (float)yy * (2.f / 63.f) - 1.f;
            float lx = (float)xx * (2.f / 63.f) - 1.f;
            float4 v = *(const float4*)(g_conv2 + ((b * 64 + yy) * 64 + xx) * 64 + c0);
            float k0 = fmaxf(1.f - 0.5f * (fabsf(ly - mux0) + fabsf(lx - muy0)), -1.f);
            float k1 = fmaxf(1.f - 0.5f * (fabsf(ly - mux1) + fabsf(lx - muy1)), -1.f);
            float k2 = fmaxf(1.f - 0.5f * (fabsf(ly - mux2) + fabsf(lx - muy2)), -1.f);
            float k3 = fmaxf(1.f - 0.5f * (fabsf(ly - mux3) + fabsf(lx - muy3)), -1.f);
            m.x = fmaxf(m.x, v.x * k0);
            m.y = fmaxf(m.y, v.y * k1);
            m.z = fmaxf(m.z, v.z * k2);
            m.w = fmaxf(m.w, v.w * k3);
        }
    }
    ((float4*)outp)[idx] = m;
}

// ---------------- K4: dense1 split-K, cp.async double-buffered w-tiles -------
// (R14 measured-best version: 2n x 32b compute from ring.)
#define D1_SMEM (128 * 36 * 4 + 2 * 16 * 512 * 4)   // 18432 + 65536 = 83968
__global__ void __launch_bounds__(256, 2) k_dense1(const float* __restrict__ x,
                                                   const float* __restrict__ w) {
    extern __shared__ __align__(16) float dyn[];
    float* xs = dyn;                  // [128][36]
    float* wbuf = dyn + 128 * 36;     // [2][16][512]

    int tid = threadIdx.x;
    int n0 = blockIdx.x * 512 + tid * 2;
    long kbase = (long)blockIdx.y * 512;
    const float* wbase = w + kbase * 1024 + blockIdx.x * 512;

    int c_row[8], c_col[8];
#pragma unroll
    for (int j = 0; j < 8; j++) {
        int c = tid + j * 256;
        c_row[j] = c >> 7;            // 0..15
        c_col[j] = (c & 127) << 2;    // float offset in 512-row
    }

#define D1_PREFETCH(st)                                                        \
    do {                                                                       \
        const float* _src = wbase + (long)(st) * 16 * 1024;                    \
        float* _dst = wbuf + ((st) & 1) * 8192;                                \
        _Pragma("unroll")                                                      \
        for (int _j = 0; _j < 8; _j++) {                                       \
            unsigned _d = (unsigned)__cvta_generic_to_shared(                  \
                _dst + c_row[_j] * 512 + c_col[_j]);                           \
            asm volatile("cp.async.cg.shared.global [%0], [%1], 16;"           \
                         :: "r"(_d), "l"(_src + c_row[_j] * 1024 + c_col[_j])  \
                         : "memory");                                          \
        }                                                                      \
    } while (0)

    float2 a0[16], a1[16];
#pragma unroll
    for (int i = 0; i < 16; i++) {
        a0[i] = make_float2(0.f, 0.f);
        a1[i] = make_float2(0.f, 0.f);
    }

    D1_PREFETCH(0);
    asm volatile("cp.async.commit_group;" ::: "memory");
    D1_PREFETCH(1);
    asm volatile("cp.async.commit_group;" ::: "memory");

    for (int t = 0; t < 4; t++) {
        __syncthreads();
        for (int i = tid; i < 4096; i += 256) {
            int kk = i & 127, bb = i >> 7;
            xs[kk * 36 + bb] = x[bb * 65536 + kbase + t * 128 + kk];
        }
        for (int s = 0; s < 8; s++) {
            int st = t * 8 + s;
            asm volatile("cp.async.wait_group 1;" ::: "memory");
            __syncthreads();

            const float* wrow = wbuf + (st & 1) * 8192 + tid * 2;
            const float* xrow = xs + (s * 16) * 36;
#pragma unroll 4
            for (int kk = 0; kk < 16; kk++) {
                float2 wv = *(const float2*)(wrow + kk * 512);
                float2 w0; w0.x = wv.x; w0.y = wv.x;
                float2 w1; w1.x = wv.y; w1.y = wv.y;
                const float4* xp = (const float4*)(xrow + kk * 36);
#pragma unroll
                for (int q = 0; q < 8; q++) {
                    float4 xv = xp[q];
                    float2 lo; lo.x = xv.x; lo.y = xv.y;
                    float2 hi; hi.x = xv.z; hi.y = xv.w;
                    a0[2 * q]     = ffma2(lo, w0, a0[2 * q]);
                    a0[2 * q + 1] = ffma2(hi, w0, a0[2 * q + 1]);
                    a1[2 * q]     = ffma2(lo, w1, a1[2 * q]);
                    a1[2 * q + 1] = ffma2(hi, w1, a1[2 * q + 1]);
                }
            }
            __syncthreads();
            if (st + 2 < 32) D1_PREFETCH(st + 2);
            asm volatile("cp.async.commit_group;" ::: "memory");
        }
    }

    float* p = g_part + (size_t)blockIdx.y * 32 * 1024;
#pragma unroll
    for (int bb = 0; bb < 16; bb++) {
        p[(2 * bb) * 1024 + n0]         = a0[bb].x;
        p[(2 * bb + 1) * 1024 + n0]     = a0[bb].y;
        p[(2 * bb) * 1024 + n0 + 1]     = a1[bb].x;
        p[(2 * bb + 1) * 1024 + n0 + 1] = a1[bb].y;
    }
#undef D1_PREFETCH
}

// ---------------- K5: segment-mean -> argmax category per filter -------------
__global__ void k_filters(const int* __restrict__ lab32,
                          float* __restrict__ outf) {
    __shared__ float sc[2048];      // csum[b][c]
    __shared__ float mean[10][64];
    __shared__ int lbl[32];
    int tid = threadIdx.x;

    for (int i = tid; i < 2048; i += 640) {
        int b = i >> 6, c = i & 63;
        float s = 0.f;
#pragma unroll
        for (int t = 0; t < 16; t++) s += g_psum[(b * 16 + t) * 64 + c];
        sc[i] = s;
    }
    if (tid == 0) {
        bool is64 = true;
        for (int i = 1; i < 32; i += 2)
            if (lab32[i] != 0) { is64 = false; break; }
        if (is64) {
            const long long* l64 = (const long long*)lab32;
            for (int b = 0; b < 32; b++) lbl[b] = (int)l64[b];
        } else {
            for (int b = 0; b < 32; b++) lbl[b] = lab32[b];
        }
    }
    __syncthreads();

    {
        int cat = tid / 64, c = tid & 63;
        float s = 0.f; int ct = 0;
        for (int b = 0; b < 32; b++) {
            if (lbl[b] == cat) { s += sc[b * 64 + c]; ct++; }
        }
        mean[cat][c] = s / (float)ct;         // ct==0 -> NaN (numpy: NaN wins)
    }
    __syncthreads();

    if (tid < 64) {
        float best = 0.f;
        int bi = 0;
        bool have = false, bnan = false;
        for (int cat = 0; cat < 10; cat++) {
            float v = mean[cat][tid];
            bool vn = isnan(v);
            if (!bnan && (vn || !have || v > best)) {
                best = v; bi = cat; bnan = vn; have = true;
            }
        }
        outf[tid] = (float)bi;
    }
}

// ---------------- K6: reduce partials + bias + relu --------------------------
__global__ void k_dense1_fin(const float* __restrict__ bias) {
    int idx = blockIdx.x * 256 + threadIdx.x;   // 32*1024
    int n = idx & 1023, b = idx >> 10;
    float s = 0.f;
#pragma unroll 16
    for (int ks = 0; ks < 128; ks++) s += g_part[(ks * 32 + b) * 1024 + n];
    g_hidden[idx] = fmaxf(s + bias[n], 0.f);
}

// ---------------- K7: dense2 -> logits (k-parallel + smem tree) --------------
__global__ void k_dense2(const float* __restrict__ w,
                         const float* __restrict__ bias,
                         float* __restrict__ logits) {
    int b = blockIdx.x;            // 32
    int tid = threadIdx.x;         // 256
    float acc[10];
#pragma unroll
    for (int j = 0; j < 10; j++) acc[j] = 0.f;
    const float* h = g_hidden + b * 1024;
#pragma unroll
    for (int t = 0; t < 4; t++) {
        int k = t * 256 + tid;
        float hv = h[k];
        const float* wr = w + k * 10;
#pragma unroll
        for (int j = 0; j < 10; j++) acc[j] = fmaf(hv, wr[j], acc[j]);
    }
    __shared__ float s[256 * 10];
#pragma unroll
    for (int j = 0; j < 10; j++) s[tid * 10 + j] = acc[j];
    __syncthreads();
    for (int off = 128; off > 0; off >>= 1) {
        if (tid < off) {
#pragma unroll
            for (int j = 0; j < 10; j++)
                s[tid * 10 + j] += s[(tid + off) * 10 + j];
        }
        __syncthreads();
    }
    if (tid < 10) logits[b * 10 + tid] = s[tid] + bias[tid];
}

// ---------------- launcher ---------------------------------------------------
extern "C" void kernel_launch(void* const* d_in, const int* in_sizes, int n_in,
                              void* d_out, int out_size) {
    const float* inputs = (const float*)d_in[0];
    const int*   labels = (const int*)d_in[1];   // dtype resolved on-device
    const float* c1w = (const float*)d_in[2];
    const float* c1b = (const float*)d_in[3];
    const float* c2w = (const float*)d_in[4];
    const float* c2b = (const float*)d_in[5];
    const float* d1w = (const float*)d_in[6];
    const float* d1b = (const float*)d_in[7];
    const float* d2w = (const float*)d_in[8];
    const float* d2b = (const float*)d_in[9];

    float* out = (float*)d_out;
    float* out_logits = out;                       // (32,10)
    float* out_pool   = out + 320;                 // (32,32,32,64)
    float* out_filt   = out + 320 + 2097152;       // (64,)

    static int smem_set = 0;
    if (!smem_set) {
        cudaFuncSetAttribute(k_conv2, cudaFuncAttributeMaxDynamicSharedMemorySize,
                             CONV2_SMEM);
        cudaFuncSetAttribute(k_dense1, cudaFuncAttributeMaxDynamicSharedMemorySize,
                             D1_SMEM);
        smem_set = 1;
    }

    k_conv1_pool<<<4096, 256>>>(inputs, c1w, c1b);
    k_nop<<<1, 1>>>();                 // slot-align: ncu profiles launch idx 3
    k_nop<<<1, 1>>>();
    k_conv2<<<512, 256, CONV2_SMEM>>>(c2w, c2b);
    k_maskpool<<<2048, 256>>>(out_pool);
    k_dense1<<<dim3(2, 128), 256, D1_SMEM>>>(out_pool, d1w);
    k_filters<<<1, 640>>>(labels, out_filt);
    k_dense1_fin<<<128, 256>>>(d1b);
    k_dense2<<<32, 256>>>(d2w, d2b, out_logits);
}